// round 5
// baseline (speedup 1.0000x reference)
#include <cuda_runtime.h>
#include <math.h>
#include <stdint.h>

#define Bb 128
#define Tt 128
#define Vv 10000
#define Ee 256
#define Hh 1024
#define Dd 128
#define G3 3072           // 3*H
#define MROWS (Bb*Tt)     // 16384
#define NJT 48            // j-tiles of 64
#define NKS 3             // k-splits
#define GRID_GRU (NJT*NKS)   // 144 CTAs, all co-resident (<=148 SMs)

// ---------------- scratch (__device__ globals: allowed) --------------------
__device__ float g_xg[MROWS * G3];       // [T][B][3H] input-side preacts (incl bi)
__device__ float g_hs[MROWS * Hh];       // [T][B][H]
__device__ float g_d [MROWS * Dd];
__device__ float g_rgp[NKS * Bb * G3];   // recurrent matmul partials per k-split
__device__ float g_hT[Hh * Bb];          // h_t transposed [k][b]
__device__ float g_rkdup[Hh * G3 * 2];   // rk with each element duplicated: [k][2j],[2j+1]
__device__ unsigned g_bar;

__global__ void k_reset() { g_bar = 0u; }

// ---------------- PTX helpers ----------------------------------------------
__device__ __forceinline__ uint32_t smem_to_u32(const void* p) {
    uint32_t a;
    asm("{ .reg .u64 t; cvta.to.shared.u64 t, %1; cvt.u32.u64 %0, t; }"
        : "=r"(a) : "l"(p));
    return a;
}
__device__ __forceinline__ void cp16(uint32_t dst, const void* src) {
    asm volatile("cp.async.cg.shared.global [%0], [%1], 16;" :: "r"(dst), "l"(src));
}
#define CP_COMMIT() asm volatile("cp.async.commit_group;" ::: "memory")
#define CP_WAIT(n)  asm volatile("cp.async.wait_group %0;" :: "n"(n) : "memory")

// packed fp32x2 fma: acc = a*b + acc  (elementwise on 2-lane packs)
#define FMA2(acc, a, b) \
    asm("fma.rn.f32x2 %0, %1, %2, %0;" : "+l"(acc) : "l"(a), "l"(b))

__device__ __forceinline__ float sig_(float x) { return 1.f / (1.f + expf(-x)); }

// SMEM: HT[2][32][128] f32 + RD[2][32][128] f32 = 64 KB dynamic
#define CHUNK_K 32
#define TILE_F  (CHUNK_K * 128)         // floats per tile
#define TILE_B  (TILE_F * 4)            // 16384 bytes
#define GRU_SMEM (4 * TILE_B)           // 65536

// ---------------------------------------------------------------------------
// prep: rkdup[k][2j] = rkdup[k][2j+1] = rk[k][j]
// ---------------------------------------------------------------------------
__global__ __launch_bounds__(256) void k_rkdup(const float* __restrict__ rk)
{
    int i = blockIdx.x * 256 + threadIdx.x;      // over 1024*3072
    float v = rk[i];
    int k = i / G3, j = i % G3;
    *reinterpret_cast<float2*>(&g_rkdup[(size_t)k * (G3 * 2) + 2 * j]) =
        make_float2(v, v);
}

// ---------------------------------------------------------------------------
// Kernel 1: xg = emb[tokens] @ gru_k + gru_bi   (fp32)
// ---------------------------------------------------------------------------
__global__ __launch_bounds__(256) void k_embed_gemm(
    const int* __restrict__ tokens, const float* __restrict__ emb,
    const float* __restrict__ gk, const float* __restrict__ bi)
{
    __shared__ float As[16][68];
    __shared__ float Bs[16][68];
    const int n0 = blockIdx.x * 64;
    const int m0 = blockIdx.y * 64;
    const int tid = threadIdx.x;
    const int tx = tid & 15, ty = tid >> 4;
    const int a_row = tid >> 2, a_c4 = tid & 3;
    const int b_row = tid >> 4, b_c4 = tid & 15;
    const int r = m0 + a_row;
    const int tok = tokens[(r & 127) * Tt + (r >> 7)];
    const float4* __restrict__ apt =
        reinterpret_cast<const float4*>(emb + (size_t)tok * Ee);

    float acc[4][4];
#pragma unroll
    for (int i = 0; i < 4; i++)
#pragma unroll
        for (int j = 0; j < 4; j++) acc[i][j] = 0.f;

    for (int k0 = 0; k0 < Ee; k0 += 16) {
        float4 av = apt[(k0 >> 2) + a_c4];
        float4 bv = *reinterpret_cast<const float4*>(
            gk + (size_t)(k0 + b_row) * G3 + n0 + b_c4 * 4);
        As[a_c4 * 4 + 0][a_row] = av.x;
        As[a_c4 * 4 + 1][a_row] = av.y;
        As[a_c4 * 4 + 2][a_row] = av.z;
        As[a_c4 * 4 + 3][a_row] = av.w;
        *reinterpret_cast<float4*>(&Bs[b_row][b_c4 * 4]) = bv;
        __syncthreads();
#pragma unroll
        for (int kk = 0; kk < 16; kk++) {
            float4 a = *reinterpret_cast<const float4*>(&As[kk][ty * 4]);
            float4 b = *reinterpret_cast<const float4*>(&Bs[kk][tx * 4]);
            float aa[4] = {a.x, a.y, a.z, a.w};
            float bb[4] = {b.x, b.y, b.z, b.w};
#pragma unroll
            for (int i = 0; i < 4; i++)
#pragma unroll
                for (int j = 0; j < 4; j++)
                    acc[i][j] = fmaf(aa[i], bb[j], acc[i][j]);
        }
        __syncthreads();
    }
#pragma unroll
    for (int i = 0; i < 4; i++) {
        int row = m0 + ty * 4 + i;
        float4 o;
        int col = n0 + tx * 4;
        o.x = acc[i][0] + bi[col + 0];
        o.y = acc[i][1] + bi[col + 1];
        o.z = acc[i][2] + bi[col + 2];
        o.w = acc[i][3] + bi[col + 3];
        *reinterpret_cast<float4*>(&g_xg[(size_t)row * G3 + col]) = o;
    }
}

// ---------------------------------------------------------------------------
// Kernel 2: persistent GRU with packed f32x2 FMA.
// 144 CTAs = 48 j-tiles(64 cols) x 3 k-splits(352/352/320).
// Phase A (t>0): rgp[ks][b][j] = sum_k hT[k][b] * rk[k][j] over k-slice.
//   inner loop: batch-pair packed FMA2; h pairs native from hT; rk dup from rkdup.
// Phase B: gate math -> h_t (g_hs + g_hT).
// ---------------------------------------------------------------------------
__global__ __launch_bounds__(256, 1) void k_gru_x2(const float* __restrict__ br)
{
    extern __shared__ char smem[];
    float* const sf = reinterpret_cast<float*>(smem);
    const uint32_t sb = smem_to_u32(smem);
    const int tid = threadIdx.x;
    const int tx = tid & 15;                 // j group: 4 j each
    const int ty = tid >> 4;                 // b group: 8 b each (4 pairs)
    const int jt = blockIdx.x % NJT;
    const int ks = blockIdx.x / NJT;         // 0..2
    const int j0 = jt * 64;
    const int kbase = ks * 352;
    const int nch = (ks == 2) ? 10 : 11;     // chunks of 32 k

    // loader: 32 rows/chunk, 8 threads/row, 4 iters of 16B
    const int lr = tid >> 3;
    const int lu = tid & 7;

    unsigned epoch = 0;

    for (int t = 0; t < Tt; t++) {
        if (t > 0) {
            // ---------------- phase A ----------------
            unsigned long long acc[4][4];
#pragma unroll
            for (int i = 0; i < 4; i++)
#pragma unroll
                for (int j = 0; j < 4; j++) acc[i][j] = 0ull;

            // preload chunks 0,1
#pragma unroll
            for (int c = 0; c < 2; c++) {
                const int krow = kbase + c * CHUNK_K + lr;
                const uint32_t hdst = sb + (c * 2) * TILE_B + (lr * 128) * 4;
                const uint32_t rdst = hdst + TILE_B;
                const float* hsrc = g_hT + (size_t)krow * 128;
                const float* rsrc = g_rkdup + (size_t)krow * (G3 * 2) + j0 * 2;
#pragma unroll
                for (int i = 0; i < 4; i++) {
                    const int u = (lu + 8 * i) * 4;
                    cp16(hdst + u * 4, hsrc + u);
                    cp16(rdst + u * 4, rsrc + u);
                }
                CP_COMMIT();
            }

            for (int c = 0; c < nch; c++) {
                if (c < nch - 2) { CP_WAIT(1); } else { CP_WAIT(0); }
                __syncthreads();
                const float* HT = sf + (c & 1) * (2 * TILE_F);
                const float* RD = HT + TILE_F;
#pragma unroll
                for (int kk = 0; kk < CHUNK_K; kk++) {
                    ulonglong2 hA = *reinterpret_cast<const ulonglong2*>(
                        HT + kk * 128 + ty * 8);
                    ulonglong2 hB = *reinterpret_cast<const ulonglong2*>(
                        HT + kk * 128 + ty * 8 + 4);
                    ulonglong2 rA = *reinterpret_cast<const ulonglong2*>(
                        RD + kk * 128 + tx * 8);
                    ulonglong2 rB = *reinterpret_cast<const ulonglong2*>(
                        RD + kk * 128 + tx * 8 + 4);
                    FMA2(acc[0][0], hA.x, rA.x); FMA2(acc[0][1], hA.x, rA.y);
                    FMA2(acc[0][2], hA.x, rB.x); FMA2(acc[0][3], hA.x, rB.y);
                    FMA2(acc[1][0], hA.y, rA.x); FMA2(acc[1][1], hA.y, rA.y);
                    FMA2(acc[1][2], hA.y, rB.x); FMA2(acc[1][3], hA.y, rB.y);
                    FMA2(acc[2][0], hB.x, rA.x); FMA2(acc[2][1], hB.x, rA.y);
                    FMA2(acc[2][2], hB.x, rB.x); FMA2(acc[2][3], hB.x, rB.y);
                    FMA2(acc[3][0], hB.y, rA.x); FMA2(acc[3][1], hB.y, rA.y);
                    FMA2(acc[3][2], hB.y, rB.x); FMA2(acc[3][3], hB.y, rB.y);
                }
                __syncthreads();
                if (c + 2 < nch) {
                    const int cc = c + 2;
                    const int krow = kbase + cc * CHUNK_K + lr;
                    const uint32_t hdst = sb + ((cc & 1) * 2) * TILE_B + (lr * 128) * 4;
                    const uint32_t rdst = hdst + TILE_B;
                    const float* hsrc = g_hT + (size_t)krow * 128;
                    const float* rsrc = g_rkdup + (size_t)krow * (G3 * 2) + j0 * 2;
#pragma unroll
                    for (int i = 0; i < 4; i++) {
                        const int u = (lu + 8 * i) * 4;
                        cp16(hdst + u * 4, hsrc + u);
                        cp16(rdst + u * 4, rsrc + u);
                    }
                    CP_COMMIT();
                }
            }

            // epilogue: write partials [ks][b][j]
#pragma unroll
            for (int bp = 0; bp < 4; bp++) {
                const int b = ty * 8 + 2 * bp;
#pragma unroll
                for (int jj = 0; jj < 4; jj++) {
                    union { unsigned long long u; float2 f; } v;
                    v.u = acc[bp][jj];
                    float* p = g_rgp + ((size_t)ks * Bb + b) * G3 + j0 + tx * 4 + jj;
                    p[0]  = v.f.x;
                    p[G3] = v.f.y;
                }
            }
            // grid barrier
            __syncthreads();
            if (tid == 0) {
                __threadfence();
                epoch++;
                atomicAdd(&g_bar, 1u);
                while (*(volatile unsigned*)&g_bar < epoch * GRID_GRU) { }
            }
            __syncthreads();
        }

        // ---------------- phase B: gates ----------------
        {
            const float* __restrict__ xgt = g_xg + (size_t)t * Bb * G3;
            const float* __restrict__ hprev = g_hs + (size_t)(t - 1) * Bb * Hh;
            float* __restrict__ hcur = g_hs + (size_t)t * Bb * Hh;
            for (int v = blockIdx.x * 256 + tid; v < (Bb * Hh) / 4; v += GRID_GRU * 256) {
                const int b = v >> 8;
                const int j = (v & 255) << 2;
                const size_t xb = (size_t)b * G3 + j;
                float4 xz = *(const float4*)(xgt + xb);
                float4 xr = *(const float4*)(xgt + xb + Hh);
                float4 xh = *(const float4*)(xgt + xb + 2 * Hh);
                float4 az = make_float4(0.f, 0.f, 0.f, 0.f);
                float4 ar = az, ah = az, hp = az;
                if (t > 0) {
#pragma unroll
                    for (int s = 0; s < NKS; s++) {
                        const float* rp = g_rgp + (size_t)s * Bb * G3 + xb;
                        float4 a0 = __ldcg((const float4*)(rp));
                        float4 a1 = __ldcg((const float4*)(rp + Hh));
                        float4 a2 = __ldcg((const float4*)(rp + 2 * Hh));
                        az.x += a0.x; az.y += a0.y; az.z += a0.z; az.w += a0.w;
                        ar.x += a1.x; ar.y += a1.y; ar.z += a1.z; ar.w += a1.w;
                        ah.x += a2.x; ah.y += a2.y; ah.z += a2.z; ah.w += a2.w;
                    }
                    hp = __ldcg((const float4*)(hprev + (size_t)b * Hh + j));
                }
                float4 bz = *(const float4*)(br + j);
                float4 brv = *(const float4*)(br + Hh + j);
                float4 bh = *(const float4*)(br + 2 * Hh + j);
                float4 o;
#define GATE1(C) { \
                float z = sig_(xz.C + az.C + bz.C); \
                float rg = sig_(xr.C + ar.C + brv.C); \
                float th = tanhf(xh.C + rg * (ah.C + bh.C)); \
                o.C = z * hp.C + (1.f - z) * th; }
                GATE1(x) GATE1(y) GATE1(z) GATE1(w)
#undef GATE1
                *(float4*)(hcur + (size_t)b * Hh + j) = o;
                // transposed copy for next step's phase A
                g_hT[(size_t)(j + 0) * Bb + b] = o.x;
                g_hT[(size_t)(j + 1) * Bb + b] = o.y;
                g_hT[(size_t)(j + 2) * Bb + b] = o.z;
                g_hT[(size_t)(j + 3) * Bb + b] = o.w;
            }
        }
        // grid barrier
        __syncthreads();
        if (tid == 0) {
            __threadfence();
            epoch++;
            atomicAdd(&g_bar, 1u);
            while (*(volatile unsigned*)&g_bar < epoch * GRID_GRU) { }
        }
        __syncthreads();
    }
}

// ---------------------------------------------------------------------------
// Kernel 3: d = relu(hs @ w1 + b1)
// ---------------------------------------------------------------------------
__global__ __launch_bounds__(256) void k_w1relu(
    const float* __restrict__ w1, const float* __restrict__ b1)
{
    __shared__ float As[16][68];
    __shared__ float Bs[16][68];
    const int n0 = blockIdx.x * 64;
    const int m0 = blockIdx.y * 64;
    const int tid = threadIdx.x;
    const int tx = tid & 15, ty = tid >> 4;
    const int a_row = tid >> 2, a_c4 = tid & 3;
    const int b_row = tid >> 4, b_c4 = tid & 15;
    const float* __restrict__ apt = g_hs + (size_t)(m0 + a_row) * Hh;

    float acc[4][4];
#pragma unroll
    for (int i = 0; i < 4; i++)
#pragma unroll
        for (int j = 0; j < 4; j++) acc[i][j] = 0.f;

    for (int k0 = 0; k0 < Hh; k0 += 16) {
        float4 av = *reinterpret_cast<const float4*>(apt + k0 + a_c4 * 4);
        float4 bv = *reinterpret_cast<const float4*>(
            w1 + (size_t)(k0 + b_row) * Dd + n0 + b_c4 * 4);
        As[a_c4 * 4 + 0][a_row] = av.x;
        As[a_c4 * 4 + 1][a_row] = av.y;
        As[a_c4 * 4 + 2][a_row] = av.z;
        As[a_c4 * 4 + 3][a_row] = av.w;
        *reinterpret_cast<float4*>(&Bs[b_row][b_c4 * 4]) = bv;
        __syncthreads();
#pragma unroll
        for (int kk = 0; kk < 16; kk++) {
            float4 a = *reinterpret_cast<const float4*>(&As[kk][ty * 4]);
            float4 b = *reinterpret_cast<const float4*>(&Bs[kk][tx * 4]);
            float aa[4] = {a.x, a.y, a.z, a.w};
            float bb[4] = {b.x, b.y, b.z, b.w};
#pragma unroll
            for (int i = 0; i < 4; i++)
#pragma unroll
                for (int j = 0; j < 4; j++)
                    acc[i][j] = fmaf(aa[i], bb[j], acc[i][j]);
        }
        __syncthreads();
    }
#pragma unroll
    for (int i = 0; i < 4; i++) {
        int row = m0 + ty * 4 + i;
        int col = n0 + tx * 4;
        float4 o;
        o.x = fmaxf(acc[i][0] + b1[col + 0], 0.f);
        o.y = fmaxf(acc[i][1] + b1[col + 1], 0.f);
        o.z = fmaxf(acc[i][2] + b1[col + 2], 0.f);
        o.w = fmaxf(acc[i][3] + b1[col + 3], 0.f);
        *reinterpret_cast<float4*>(&g_d[(size_t)row * Dd + col]) = o;
    }
}

// ---------------------------------------------------------------------------
// Kernel 4: logits = d @ w2 + b2 -> d_out as [B][T][V]
// ---------------------------------------------------------------------------
__global__ __launch_bounds__(256) void k_w2(
    const float* __restrict__ w2, const float* __restrict__ b2,
    float* __restrict__ out)
{
    __shared__ float As[16][68];
    __shared__ float Bs[16][68];
    const int n0 = blockIdx.x * 64;
    const int m0 = blockIdx.y * 64;
    const int tid = threadIdx.x;
    const int tx = tid & 15, ty = tid >> 4;
    const int a_row = tid >> 2, a_c4 = tid & 3;
    const int b_row = tid >> 4, b_c4 = tid & 15;
    const float* __restrict__ apt = g_d + (size_t)(m0 + a_row) * Dd;
    const bool full = (n0 + 64 <= Vv);

    float acc[4][4];
#pragma unroll
    for (int i = 0; i < 4; i++)
#pragma unroll
        for (int j = 0; j < 4; j++) acc[i][j] = 0.f;

    for (int k0 = 0; k0 < Dd; k0 += 16) {
        float4 av = *reinterpret_cast<const float4*>(apt + k0 + a_c4 * 4);
        As[a_c4 * 4 + 0][a_row] = av.x;
        As[a_c4 * 4 + 1][a_row] = av.y;
        As[a_c4 * 4 + 2][a_row] = av.z;
        As[a_c4 * 4 + 3][a_row] = av.w;
        if (full) {
            float4 bv = *reinterpret_cast<const float4*>(
                w2 + (size_t)(k0 + b_row) * Vv + n0 + b_c4 * 4);
            *reinterpret_cast<float4*>(&Bs[b_row][b_c4 * 4]) = bv;
        } else {
#pragma unroll
            for (int c = 0; c < 4; c++) {
                int col = n0 + b_c4 * 4 + c;
                Bs[b_row][b_c4 * 4 + c] =
                    (col < Vv) ? w2[(size_t)(k0 + b_row) * Vv + col] : 0.f;
            }
        }
        __syncthreads();
#pragma unroll
        for (int kk = 0; kk < 16; kk++) {
            float4 a = *reinterpret_cast<const float4*>(&As[kk][ty * 4]);
            float4 b = *reinterpret_cast<const float4*>(&Bs[kk][tx * 4]);
            float aa[4] = {a.x, a.y, a.z, a.w};
            float bb[4] = {b.x, b.y, b.z, b.w};
#pragma unroll
            for (int i = 0; i < 4; i++)
#pragma unroll
                for (int j = 0; j < 4; j++)
                    acc[i][j] = fmaf(aa[i], bb[j], acc[i][j]);
        }
        __syncthreads();
    }
#pragma unroll
    for (int i = 0; i < 4; i++) {
        int rr = m0 + ty * 4 + i;
        int t = rr >> 7, b = rr & 127;
        size_t obase = ((size_t)b * Tt + t) * Vv;
#pragma unroll
        for (int j = 0; j < 4; j++) {
            int col = n0 + tx * 4 + j;
            if (col < Vv) out[obase + col] = acc[i][j] + b2[col];
        }
    }
}

// ---------------------------------------------------------------------------
// Kernel 5: softmax rows of 10000 with logits*50
// ---------------------------------------------------------------------------
__global__ __launch_bounds__(256) void k_softmax(float* __restrict__ out)
{
    float* __restrict__ p = out + (size_t)blockIdx.x * Vv;
    const int tid = threadIdx.x;
    float vals[40];
    float mx = -1e30f;
#pragma unroll
    for (int i = 0; i < 40; i++) {
        int idx = tid + (i << 8);
        if (idx < Vv) {
            float v = p[idx] * 50.0f;
            vals[i] = v;
            mx = fmaxf(mx, v);
        } else {
            vals[i] = -1e30f;
        }
    }
    __shared__ float redm[8];
    __shared__ float reds[8];
#pragma unroll
    for (int o = 16; o; o >>= 1) mx = fmaxf(mx, __shfl_xor_sync(0xffffffffu, mx, o));
    if ((tid & 31) == 0) redm[tid >> 5] = mx;
    __syncthreads();
    mx = redm[0];
#pragma unroll
    for (int w = 1; w < 8; w++) mx = fmaxf(mx, redm[w]);

    float s = 0.f;
#pragma unroll
    for (int i = 0; i < 40; i++) {
        int idx = tid + (i << 8);
        if (idx < Vv) {
            float e = expf(vals[i] - mx);
            vals[i] = e;
            s += e;
        }
    }
#pragma unroll
    for (int o = 16; o; o >>= 1) s += __shfl_xor_sync(0xffffffffu, s, o);
    if ((tid & 31) == 0) reds[tid >> 5] = s;
    __syncthreads();
    float tot = 0.f;
#pragma unroll
    for (int w = 0; w < 8; w++) tot += reds[w];
    float inv = 1.0f / tot;
#pragma unroll
    for (int i = 0; i < 40; i++) {
        int idx = tid + (i << 8);
        if (idx < Vv) p[idx] = vals[i] * inv;
    }
}

// ---------------------------------------------------------------------------
extern "C" void kernel_launch(void* const* d_in, const int* in_sizes, int n_in,
                              void* d_out, int out_size)
{
    const int*   tokens = (const int*)  d_in[0];
    const float* emb    = (const float*)d_in[1];
    const float* gk     = (const float*)d_in[2];
    const float* grk    = (const float*)d_in[3];
    const float* gbi    = (const float*)d_in[4];
    const float* gbr    = (const float*)d_in[5];
    const float* w1     = (const float*)d_in[6];
    const float* b1     = (const float*)d_in[7];
    const float* w2     = (const float*)d_in[8];
    const float* b2     = (const float*)d_in[9];
    float* out = (float*)d_out;

    cudaFuncSetAttribute(k_gru_x2, cudaFuncAttributeMaxDynamicSharedMemorySize, GRU_SMEM);

    dim3 blk(256);
    k_reset<<<1, 1>>>();
    k_rkdup<<<(Hh * G3) / 256, blk>>>(grk);
    k_embed_gemm<<<dim3(G3 / 64, MROWS / 64), blk>>>(tokens, emb, gk, gbi);
    k_gru_x2<<<GRID_GRU, blk, GRU_SMEM>>>(gbr);
    k_w1relu<<<dim3(Dd / 64, MROWS / 64), blk>>>(w1, b1);
    k_w2<<<dim3((Vv + 63) / 64, MROWS / 64), blk>>>(w2, b2, out);
    k_softmax<<<MROWS, blk>>>(out);
}

// round 6
// speedup vs baseline: 1.4907x; 1.4907x over previous
#include <cuda_runtime.h>
#include <cuda_bf16.h>
#include <math.h>
#include <stdint.h>

#define Bb 128
#define Tt 128
#define Vv 10000
#define Ee 256
#define Hh 1024
#define Dd 128
#define G3 3072           // 3*H
#define MROWS (Bb*Tt)     // 16384
#define NKS 4             // k-splits of 256
#define NNT 24            // n-tiles of 128
#define GRID_GRU (NKS*NNT)   // 96 CTAs, all co-resident

// ---------------- scratch (__device__ globals: allowed) --------------------
__device__ float g_xg[MROWS * G3];       // [T][B][3H] input-side preacts (incl bi)
__device__ float g_hs[MROWS * Hh];       // [T][B][H]
__device__ float g_d [MROWS * Dd];
__device__ float g_rgp[NKS * Bb * G3];   // recurrent matmul partials per k-split
__device__ __nv_bfloat16 g_rkT_hi[G3 * Hh];  // rk^T split hi  [n][k]
__device__ __nv_bfloat16 g_rkT_lo[G3 * Hh];  // rk^T split lo
__device__ __nv_bfloat16 g_hhi[Bb * Hh];     // h_t split hi [b][k]
__device__ __nv_bfloat16 g_hlo[Bb * Hh];     // h_t split lo
__device__ unsigned g_bar;

__global__ void k_reset() { g_bar = 0u; }

// ---------------- PTX helpers ----------------------------------------------
__device__ __forceinline__ uint32_t smem_to_u32(const void* p) {
    uint32_t a;
    asm("{ .reg .u64 t; cvta.to.shared.u64 t, %1; cvt.u32.u64 %0, t; }"
        : "=r"(a) : "l"(p));
    return a;
}
__device__ __forceinline__ void ldsm_x4(uint32_t* r, uint32_t addr) {
    asm volatile("ldmatrix.sync.aligned.m8n8.x4.shared.b16 {%0,%1,%2,%3}, [%4];"
        : "=r"(r[0]), "=r"(r[1]), "=r"(r[2]), "=r"(r[3]) : "r"(addr));
}
__device__ __forceinline__ void mma_16816(float* d, const uint32_t* a, const uint32_t* b) {
    asm volatile("mma.sync.aligned.m16n8k16.row.col.f32.bf16.bf16.f32 "
        "{%0,%1,%2,%3}, {%4,%5,%6,%7}, {%8,%9}, {%0,%1,%2,%3};"
        : "+f"(d[0]), "+f"(d[1]), "+f"(d[2]), "+f"(d[3])
        : "r"(a[0]), "r"(a[1]), "r"(a[2]), "r"(a[3]), "r"(b[0]), "r"(b[1]));
}
__device__ __forceinline__ void cp16(uint32_t dst, const void* src) {
    asm volatile("cp.async.cg.shared.global [%0], [%1], 16;" :: "r"(dst), "l"(src));
}
#define CP_COMMIT() asm volatile("cp.async.commit_group;" ::: "memory")
#define CP_WAIT(n)  asm volatile("cp.async.wait_group %0;" :: "n"(n) : "memory")

__device__ __forceinline__ float sig_(float x) { return 1.f / (1.f + expf(-x)); }

// SMEM layout (dynamic):
//   A (h tile, persistent per step): 128 rows x 256 bf16, stride 528B, hi+lo
//   B (rk chunks): 2 buffers x (128 rows x 64 bf16, stride 144B, hi+lo)
#define ASTRIDE 528
#define A_HI 0
#define A_LO 67584            // 128*528
#define A_TOT 135168
#define BSTRIDE 144
#define BHALF 18432           // 128*144
#define BBUF  36864           // hi+lo
#define B_BASE A_TOT
#define GRU_SMEM (A_TOT + 2*BBUF)   // 208896 B

// ---------------------------------------------------------------------------
// init: split + transpose rk [K=1024][N=3072] -> rkT hi/lo [N=3072][K=1024]
// ---------------------------------------------------------------------------
__global__ __launch_bounds__(256) void k_rk_split(const float* __restrict__ rk)
{
    __shared__ float tile[32][33];
    const int n0 = blockIdx.x * 32, k0 = blockIdx.y * 32;
    const int tx = threadIdx.x & 31, ty = threadIdx.x >> 5;  // ty 0..7
#pragma unroll
    for (int i = 0; i < 4; i++)
        tile[ty + 8 * i][tx] = rk[(size_t)(k0 + ty + 8 * i) * G3 + n0 + tx];
    __syncthreads();
#pragma unroll
    for (int i = 0; i < 4; i++) {
        int n = n0 + ty + 8 * i;
        float v = tile[tx][ty + 8 * i];
        __nv_bfloat16 hi = __float2bfloat16(v);
        __nv_bfloat16 lo = __float2bfloat16(v - __bfloat162float(hi));
        g_rkT_hi[(size_t)n * Hh + k0 + tx] = hi;
        g_rkT_lo[(size_t)n * Hh + k0 + tx] = lo;
    }
}

// ---------------------------------------------------------------------------
// Kernel 1: xg = emb[tokens] @ gru_k + gru_bi   (fp32)
// ---------------------------------------------------------------------------
__global__ __launch_bounds__(256) void k_embed_gemm(
    const int* __restrict__ tokens, const float* __restrict__ emb,
    const float* __restrict__ gk, const float* __restrict__ bi)
{
    __shared__ float As[16][68];
    __shared__ float Bs[16][68];
    const int n0 = blockIdx.x * 64;
    const int m0 = blockIdx.y * 64;
    const int tid = threadIdx.x;
    const int tx = tid & 15, ty = tid >> 4;
    const int a_row = tid >> 2, a_c4 = tid & 3;
    const int b_row = tid >> 4, b_c4 = tid & 15;
    const int r = m0 + a_row;
    const int tok = tokens[(r & 127) * Tt + (r >> 7)];
    const float4* __restrict__ apt =
        reinterpret_cast<const float4*>(emb + (size_t)tok * Ee);

    float acc[4][4];
#pragma unroll
    for (int i = 0; i < 4; i++)
#pragma unroll
        for (int j = 0; j < 4; j++) acc[i][j] = 0.f;

    for (int k0 = 0; k0 < Ee; k0 += 16) {
        float4 av = apt[(k0 >> 2) + a_c4];
        float4 bv = *reinterpret_cast<const float4*>(
            gk + (size_t)(k0 + b_row) * G3 + n0 + b_c4 * 4);
        As[a_c4 * 4 + 0][a_row] = av.x;
        As[a_c4 * 4 + 1][a_row] = av.y;
        As[a_c4 * 4 + 2][a_row] = av.z;
        As[a_c4 * 4 + 3][a_row] = av.w;
        *reinterpret_cast<float4*>(&Bs[b_row][b_c4 * 4]) = bv;
        __syncthreads();
#pragma unroll
        for (int kk = 0; kk < 16; kk++) {
            float4 a = *reinterpret_cast<const float4*>(&As[kk][ty * 4]);
            float4 b = *reinterpret_cast<const float4*>(&Bs[kk][tx * 4]);
            float aa[4] = {a.x, a.y, a.z, a.w};
            float bb[4] = {b.x, b.y, b.z, b.w};
#pragma unroll
            for (int i = 0; i < 4; i++)
#pragma unroll
                for (int j = 0; j < 4; j++)
                    acc[i][j] = fmaf(aa[i], bb[j], acc[i][j]);
        }
        __syncthreads();
    }
#pragma unroll
    for (int i = 0; i < 4; i++) {
        int row = m0 + ty * 4 + i;
        float4 o;
        int col = n0 + tx * 4;
        o.x = acc[i][0] + bi[col + 0];
        o.y = acc[i][1] + bi[col + 1];
        o.z = acc[i][2] + bi[col + 2];
        o.w = acc[i][3] + bi[col + 3];
        *reinterpret_cast<float4*>(&g_xg[(size_t)row * G3 + col]) = o;
    }
}

// ---------------------------------------------------------------------------
// Kernel 2: persistent GRU, mma.sync bf16 3-pass split, rebuilt pipeline.
// 96 CTAs = 24 n-tiles(128) x 4 k-splits(256).
// Phase A: A(h hi+lo) loaded once into smem; B(rk) streamed 4x double-buffered.
// ---------------------------------------------------------------------------
__global__ __launch_bounds__(256, 1) void k_gru_mma2(const float* __restrict__ br)
{
    extern __shared__ char smem[];
    const uint32_t sb = smem_to_u32(smem);
    const int tid = threadIdx.x;
    const int lane = tid & 31;
    const int wid = tid >> 5;
    const int ntile = blockIdx.x % NNT;
    const int ks    = blockIdx.x / NNT;        // 0..3
    const int n0    = ntile * 128;
    const int kbase = ks * 256;
    const int mbase = (wid & 1) * 64;          // warp M rows (batch)
    const int nbase = (wid >> 1) * 32;         // warp N cols within tile

    // loader geometry: thread t -> row t>>1, half t&1
    const int lrow = tid >> 1;
    const int lhalf = tid & 1;
    // ldmatrix per-thread offsets
    const uint32_t aoff = (uint32_t)((lane & 15) * ASTRIDE + ((lane >> 4) & 1) * 16);
    const uint32_t boff = (uint32_t)((((lane & 7) + ((lane >> 4) & 1) * 8)) * BSTRIDE
                                     + ((lane >> 3) & 1) * 16);

    unsigned epoch = 0;

    for (int t = 0; t < Tt; t++) {
        if (t > 0) {
            // ---- issue A (group), B0 (group), B1 (group) ----
            {
                const uint32_t adh = sb + A_HI + lrow * ASTRIDE + lhalf * 256;
                const uint32_t adl = sb + A_LO + lrow * ASTRIDE + lhalf * 256;
                const char* ash = (const char*)(g_hhi + (size_t)lrow * Hh + kbase + lhalf * 128);
                const char* asl = (const char*)(g_hlo + (size_t)lrow * Hh + kbase + lhalf * 128);
#pragma unroll
                for (int i = 0; i < 16; i++) {
                    cp16(adh + i * 16, ash + i * 16);
                    cp16(adl + i * 16, asl + i * 16);
                }
                CP_COMMIT();
#pragma unroll
                for (int c = 0; c < 2; c++) {
                    const uint32_t bd = sb + B_BASE + c * BBUF + lrow * BSTRIDE + lhalf * 64;
                    const char* bsh = (const char*)(g_rkT_hi + (size_t)(n0 + lrow) * Hh
                                                    + kbase + c * 64 + lhalf * 32);
                    const char* bsl = (const char*)(g_rkT_lo + (size_t)(n0 + lrow) * Hh
                                                    + kbase + c * 64 + lhalf * 32);
#pragma unroll
                    for (int i = 0; i < 4; i++) {
                        cp16(bd + i * 16, bsh + i * 16);
                        cp16(bd + BHALF + i * 16, bsl + i * 16);
                    }
                    CP_COMMIT();
                }
            }
            CP_WAIT(0);
            __syncthreads();

            float acc[4][4][4];
#pragma unroll
            for (int i = 0; i < 4; i++)
#pragma unroll
                for (int j = 0; j < 4; j++)
#pragma unroll
                    for (int q = 0; q < 4; q++) acc[i][j][q] = 0.f;

#pragma unroll
            for (int c = 0; c < 4; c++) {
                const uint32_t bbuf = sb + B_BASE + (c & 1) * BBUF;
                // 4 k16 steps per chunk
#pragma unroll
                for (int s = 0; s < 4; s++) {
                    const int kk = c * 4 + s;
                    uint32_t ah[4][4], al[4][4];
#pragma unroll
                    for (int mf = 0; mf < 4; mf++) {
                        const uint32_t ad = sb + A_HI + (mbase + mf * 16) * ASTRIDE
                                          + kk * 32 + aoff;
                        ldsm_x4(ah[mf], ad);
                        ldsm_x4(al[mf], ad + (A_LO - A_HI));
                    }
                    uint32_t bh[2][4], bl[2][4];
#pragma unroll
                    for (int nl = 0; nl < 2; nl++) {
                        const uint32_t bd = bbuf + (nbase + nl * 16) * BSTRIDE
                                          + s * 32 + boff;
                        ldsm_x4(bh[nl], bd);
                        ldsm_x4(bl[nl], bd + BHALF);
                    }
#pragma unroll
                    for (int mf = 0; mf < 4; mf++)
#pragma unroll
                        for (int nl = 0; nl < 2; nl++)
#pragma unroll
                            for (int h2 = 0; h2 < 2; h2++) {
                                float* a = acc[mf][nl * 2 + h2];
                                mma_16816(a, ah[mf], &bh[nl][2 * h2]);
                                mma_16816(a, ah[mf], &bl[nl][2 * h2]);
                                mma_16816(a, al[mf], &bh[nl][2 * h2]);
                            }
                }
                __syncthreads();
                if (c < 2) {
                    // refill buffer (c&1) with chunk c+2
                    const int cc = c + 2;
                    const uint32_t bd = sb + B_BASE + (c & 1) * BBUF
                                      + lrow * BSTRIDE + lhalf * 64;
                    const char* bsh = (const char*)(g_rkT_hi + (size_t)(n0 + lrow) * Hh
                                                    + kbase + cc * 64 + lhalf * 32);
                    const char* bsl = (const char*)(g_rkT_lo + (size_t)(n0 + lrow) * Hh
                                                    + kbase + cc * 64 + lhalf * 32);
#pragma unroll
                    for (int i = 0; i < 4; i++) {
                        cp16(bd + i * 16, bsh + i * 16);
                        cp16(bd + BHALF + i * 16, bsl + i * 16);
                    }
                    CP_COMMIT();
                }
                if (c == 1) { CP_WAIT(1); __syncthreads(); }
                if (c == 2) { CP_WAIT(0); __syncthreads(); }
            }

            // epilogue: write partials [ks][b][j]
#pragma unroll
            for (int mf = 0; mf < 4; mf++) {
                const int row = mbase + mf * 16 + (lane >> 2);
#pragma unroll
                for (int nf = 0; nf < 4; nf++) {
                    const float* a = acc[mf][nf];
                    const int col = n0 + nbase + nf * 8 + (lane & 3) * 2;
                    float* p = g_rgp + ((size_t)ks * Bb + row) * G3 + col;
                    *(float2*)p = make_float2(a[0], a[1]);
                    *(float2*)(p + (size_t)8 * G3) = make_float2(a[2], a[3]);
                }
            }
            // grid barrier
            __syncthreads();
            if (tid == 0) {
                __threadfence();
                epoch++;
                atomicAdd(&g_bar, 1u);
                while (*(volatile unsigned*)&g_bar < epoch * GRID_GRU) { }
            }
            __syncthreads();
        }

        // ---------------- phase B: gates ----------------
        {
            const float* __restrict__ xgt = g_xg + (size_t)t * Bb * G3;
            const float* __restrict__ hprev = g_hs + (size_t)(t - 1) * Bb * Hh;
            float* __restrict__ hcur = g_hs + (size_t)t * Bb * Hh;
            for (int v = blockIdx.x * 256 + tid; v < (Bb * Hh) / 4; v += GRID_GRU * 256) {
                const int b = v >> 8;
                const int j = (v & 255) << 2;
                const size_t xb = (size_t)b * G3 + j;
                float4 xz = *(const float4*)(xgt + xb);
                float4 xr = *(const float4*)(xgt + xb + Hh);
                float4 xh = *(const float4*)(xgt + xb + 2 * Hh);
                float4 az = make_float4(0.f, 0.f, 0.f, 0.f);
                float4 ar = az, ah = az, hp = az;
                if (t > 0) {
#pragma unroll
                    for (int s = 0; s < NKS; s++) {
                        const float* rp = g_rgp + (size_t)s * Bb * G3 + xb;
                        float4 a0 = __ldcg((const float4*)(rp));
                        float4 a1 = __ldcg((const float4*)(rp + Hh));
                        float4 a2 = __ldcg((const float4*)(rp + 2 * Hh));
                        az.x += a0.x; az.y += a0.y; az.z += a0.z; az.w += a0.w;
                        ar.x += a1.x; ar.y += a1.y; ar.z += a1.z; ar.w += a1.w;
                        ah.x += a2.x; ah.y += a2.y; ah.z += a2.z; ah.w += a2.w;
                    }
                    hp = __ldcg((const float4*)(hprev + (size_t)b * Hh + j));
                }
                float4 bz = *(const float4*)(br + j);
                float4 brv = *(const float4*)(br + Hh + j);
                float4 bh = *(const float4*)(br + 2 * Hh + j);
                float4 o;
#define GATE1(C) { \
                float z = sig_(xz.C + az.C + bz.C); \
                float rg = sig_(xr.C + ar.C + brv.C); \
                float th = tanhf(xh.C + rg * (ah.C + bh.C)); \
                o.C = z * hp.C + (1.f - z) * th; }
                GATE1(x) GATE1(y) GATE1(z) GATE1(w)
#undef GATE1
                *(float4*)(hcur + (size_t)b * Hh + j) = o;
                __nv_bfloat16 h0 = __float2bfloat16(o.x);
                __nv_bfloat16 h1 = __float2bfloat16(o.y);
                __nv_bfloat16 h2 = __float2bfloat16(o.z);
                __nv_bfloat16 h3 = __float2bfloat16(o.w);
                union { __nv_bfloat16 bf[4]; uint2 u; } ph, pl;
                ph.bf[0] = h0; ph.bf[1] = h1; ph.bf[2] = h2; ph.bf[3] = h3;
                pl.bf[0] = __float2bfloat16(o.x - __bfloat162float(h0));
                pl.bf[1] = __float2bfloat16(o.y - __bfloat162float(h1));
                pl.bf[2] = __float2bfloat16(o.z - __bfloat162float(h2));
                pl.bf[3] = __float2bfloat16(o.w - __bfloat162float(h3));
                *(uint2*)(g_hhi + (size_t)b * Hh + j) = ph.u;
                *(uint2*)(g_hlo + (size_t)b * Hh + j) = pl.u;
            }
        }
        // grid barrier
        __syncthreads();
        if (tid == 0) {
            __threadfence();
            epoch++;
            atomicAdd(&g_bar, 1u);
            while (*(volatile unsigned*)&g_bar < epoch * GRID_GRU) { }
        }
        __syncthreads();
    }
}

// ---------------------------------------------------------------------------
// Kernel 3: d = relu(hs @ w1 + b1)
// ---------------------------------------------------------------------------
__global__ __launch_bounds__(256) void k_w1relu(
    const float* __restrict__ w1, const float* __restrict__ b1)
{
    __shared__ float As[16][68];
    __shared__ float Bs[16][68];
    const int n0 = blockIdx.x * 64;
    const int m0 = blockIdx.y * 64;
    const int tid = threadIdx.x;
    const int tx = tid & 15, ty = tid >> 4;
    const int a_row = tid >> 2, a_c4 = tid & 3;
    const int b_row = tid >> 4, b_c4 = tid & 15;
    const float* __restrict__ apt = g_hs + (size_t)(m0 + a_row) * Hh;

    float acc[4][4];
#pragma unroll
    for (int i = 0; i < 4; i++)
#pragma unroll
        for (int j = 0; j < 4; j++) acc[i][j] = 0.f;

    for (int k0 = 0; k0 < Hh; k0 += 16) {
        float4 av = *reinterpret_cast<const float4*>(apt + k0 + a_c4 * 4);
        float4 bv = *reinterpret_cast<const float4*>(
            w1 + (size_t)(k0 + b_row) * Dd + n0 + b_c4 * 4);
        As[a_c4 * 4 + 0][a_row] = av.x;
        As[a_c4 * 4 + 1][a_row] = av.y;
        As[a_c4 * 4 + 2][a_row] = av.z;
        As[a_c4 * 4 + 3][a_row] = av.w;
        *reinterpret_cast<float4*>(&Bs[b_row][b_c4 * 4]) = bv;
        __syncthreads();
#pragma unroll
        for (int kk = 0; kk < 16; kk++) {
            float4 a = *reinterpret_cast<const float4*>(&As[kk][ty * 4]);
            float4 b = *reinterpret_cast<const float4*>(&Bs[kk][tx * 4]);
            float aa[4] = {a.x, a.y, a.z, a.w};
            float bb[4] = {b.x, b.y, b.z, b.w};
#pragma unroll
            for (int i = 0; i < 4; i++)
#pragma unroll
                for (int j = 0; j < 4; j++)
                    acc[i][j] = fmaf(aa[i], bb[j], acc[i][j]);
        }
        __syncthreads();
    }
#pragma unroll
    for (int i = 0; i < 4; i++) {
        int row = m0 + ty * 4 + i;
        int col = n0 + tx * 4;
        float4 o;
        o.x = fmaxf(acc[i][0] + b1[col + 0], 0.f);
        o.y = fmaxf(acc[i][1] + b1[col + 1], 0.f);
        o.z = fmaxf(acc[i][2] + b1[col + 2], 0.f);
        o.w = fmaxf(acc[i][3] + b1[col + 3], 0.f);
        *reinterpret_cast<float4*>(&g_d[(size_t)row * Dd + col]) = o;
    }
}

// ---------------------------------------------------------------------------
// Kernel 4: logits = d @ w2 + b2 -> d_out as [B][T][V]
// ---------------------------------------------------------------------------
__global__ __launch_bounds__(256) void k_w2(
    const float* __restrict__ w2, const float* __restrict__ b2,
    float* __restrict__ out)
{
    __shared__ float As[16][68];
    __shared__ float Bs[16][68];
    const int n0 = blockIdx.x * 64;
    const int m0 = blockIdx.y * 64;
    const int tid = threadIdx.x;
    const int tx = tid & 15, ty = tid >> 4;
    const int a_row = tid >> 2, a_c4 = tid & 3;
    const int b_row = tid >> 4, b_c4 = tid & 15;
    const float* __restrict__ apt = g_d + (size_t)(m0 + a_row) * Dd;
    const bool full = (n0 + 64 <= Vv);

    float acc[4][4];
#pragma unroll
    for (int i = 0; i < 4; i++)
#pragma unroll
        for (int j = 0; j < 4; j++) acc[i][j] = 0.f;

    for (int k0 = 0; k0 < Dd; k0 += 16) {
        float4 av = *reinterpret_cast<const float4*>(apt + k0 + a_c4 * 4);
        As[a_c4 * 4 + 0][a_row] = av.x;
        As[a_c4 * 4 + 1][a_row] = av.y;
        As[a_c4 * 4 + 2][a_row] = av.z;
        As[a_c4 * 4 + 3][a_row] = av.w;
        if (full) {
            float4 bv = *reinterpret_cast<const float4*>(
                w2 + (size_t)(k0 + b_row) * Vv + n0 + b_c4 * 4);
            *reinterpret_cast<float4*>(&Bs[b_row][b_c4 * 4]) = bv;
        } else {
#pragma unroll
            for (int c = 0; c < 4; c++) {
                int col = n0 + b_c4 * 4 + c;
                Bs[b_row][b_c4 * 4 + c] =
                    (col < Vv) ? w2[(size_t)(k0 + b_row) * Vv + col] : 0.f;
            }
        }
        __syncthreads();
#pragma unroll
        for (int kk = 0; kk < 16; kk++) {
            float4 a = *reinterpret_cast<const float4*>(&As[kk][ty * 4]);
            float4 b = *reinterpret_cast<const float4*>(&Bs[kk][tx * 4]);
            float aa[4] = {a.x, a.y, a.z, a.w};
            float bb[4] = {b.x, b.y, b.z, b.w};
#pragma unroll
            for (int i = 0; i < 4; i++)
#pragma unroll
                for (int j = 0; j < 4; j++)
                    acc[i][j] = fmaf(aa[i], bb[j], acc[i][j]);
        }
        __syncthreads();
    }
#pragma unroll
    for (int i = 0; i < 4; i++) {
        int rr = m0 + ty * 4 + i;
        int t = rr >> 7, b = rr & 127;
        size_t obase = ((size_t)b * Tt + t) * Vv;
#pragma unroll
        for (int j = 0; j < 4; j++) {
            int col = n0 + tx * 4 + j;
            if (col < Vv) out[obase + col] = acc[i][j] + b2[col];
        }
    }
}

// ---------------------------------------------------------------------------
// Kernel 5: softmax rows of 10000 with logits*50
// ---------------------------------------------------------------------------
__global__ __launch_bounds__(256) void k_softmax(float* __restrict__ out)
{
    float* __restrict__ p = out + (size_t)blockIdx.x * Vv;
    const int tid = threadIdx.x;
    float vals[40];
    float mx = -1e30f;
#pragma unroll
    for (int i = 0; i < 40; i++) {
        int idx = tid + (i << 8);
        if (idx < Vv) {
            float v = p[idx] * 50.0f;
            vals[i] = v;
            mx = fmaxf(mx, v);
        } else {
            vals[i] = -1e30f;
        }
    }
    __shared__ float redm[8];
    __shared__ float reds[8];
#pragma unroll
    for (int o = 16; o; o >>= 1) mx = fmaxf(mx, __shfl_xor_sync(0xffffffffu, mx, o));
    if ((tid & 31) == 0) redm[tid >> 5] = mx;
    __syncthreads();
    mx = redm[0];
#pragma unroll
    for (int w = 1; w < 8; w++) mx = fmaxf(mx, redm[w]);

    float s = 0.f;
#pragma unroll
    for (int i = 0; i < 40; i++) {
        int idx = tid + (i << 8);
        if (idx < Vv) {
            float e = expf(vals[i] - mx);
            vals[i] = e;
            s += e;
        }
    }
#pragma unroll
    for (int o = 16; o; o >>= 1) s += __shfl_xor_sync(0xffffffffu, s, o);
    if ((tid & 31) == 0) reds[tid >> 5] = s;
    __syncthreads();
    float tot = 0.f;
#pragma unroll
    for (int w = 0; w < 8; w++) tot += reds[w];
    float inv = 1.0f / tot;
#pragma unroll
    for (int i = 0; i < 40; i++) {
        int idx = tid + (i << 8);
        if (idx < Vv) p[idx] = vals[i] * inv;
    }
}

// ---------------------------------------------------------------------------
extern "C" void kernel_launch(void* const* d_in, const int* in_sizes, int n_in,
                              void* d_out, int out_size)
{
    const int*   tokens = (const int*)  d_in[0];
    const float* emb    = (const float*)d_in[1];
    const float* gk     = (const float*)d_in[2];
    const float* grk    = (const float*)d_in[3];
    const float* gbi    = (const float*)d_in[4];
    const float* gbr    = (const float*)d_in[5];
    const float* w1     = (const float*)d_in[6];
    const float* b1     = (const float*)d_in[7];
    const float* w2     = (const float*)d_in[8];
    const float* b2     = (const float*)d_in[9];
    float* out = (float*)d_out;

    cudaFuncSetAttribute(k_gru_mma2, cudaFuncAttributeMaxDynamicSharedMemorySize, GRU_SMEM);

    dim3 blk(256);
    k_reset<<<1, 1>>>();
    k_rk_split<<<dim3(G3 / 32, Hh / 32), blk>>>(grk);
    k_embed_gemm<<<dim3(G3 / 64, MROWS / 64), blk>>>(tokens, emb, gk, gbi);
    k_gru_mma2<<<GRID_GRU, blk, GRU_SMEM>>>(gbr);
    k_w1relu<<<dim3(Dd / 64, MROWS / 64), blk>>>(w1, b1);
    k_w2<<<dim3((Vv + 63) / 64, MROWS / 64), blk>>>(w2, b2, out);
    k_softmax<<<MROWS, blk>>>(out);
}

// round 7
// speedup vs baseline: 2.9220x; 1.9601x over previous
#include <cuda_runtime.h>
#include <cuda_bf16.h>
#include <math.h>
#include <stdint.h>

#define Bb 128
#define Tt 128
#define Vv 10000
#define Ee 256
#define Hh 1024
#define Dd 128
#define G3 3072           // 3*H
#define MROWS (Bb*Tt)     // 16384
#define NKS 6             // uneven k-splits: 192,192,192,192,128,128
#define NNT 24            // n-tiles of 128
#define GRID_GRU (NKS*NNT)   // 144 CTAs, all co-resident (<=148 SMs)

// ---------------- scratch (__device__ globals: allowed) --------------------
__device__ float g_xg[MROWS * G3];       // [T][B][3H] input-side preacts (incl bi)
__device__ float g_hs[MROWS * Hh];       // [T][B][H]
__device__ float g_d [MROWS * Dd];
__device__ float g_rgp[NKS * Bb * G3];   // recurrent matmul partials per k-split
__device__ __nv_bfloat16 g_rkT_hi[G3 * Hh];  // rk^T split hi  [n][k]
__device__ __nv_bfloat16 g_rkT_lo[G3 * Hh];  // rk^T split lo
__device__ __nv_bfloat16 g_hhi[Bb * Hh];     // h_t split hi [b][k]
__device__ __nv_bfloat16 g_hlo[Bb * Hh];     // h_t split lo
__device__ unsigned g_bar;

__global__ void k_reset() { g_bar = 0u; }

// ---------------- PTX helpers ----------------------------------------------
__device__ __forceinline__ uint32_t smem_to_u32(const void* p) {
    uint32_t a;
    asm("{ .reg .u64 t; cvta.to.shared.u64 t, %1; cvt.u32.u64 %0, t; }"
        : "=r"(a) : "l"(p));
    return a;
}
__device__ __forceinline__ void ldsm_x4(uint32_t* r, uint32_t addr) {
    asm volatile("ldmatrix.sync.aligned.m8n8.x4.shared.b16 {%0,%1,%2,%3}, [%4];"
        : "=r"(r[0]), "=r"(r[1]), "=r"(r[2]), "=r"(r[3]) : "r"(addr));
}
__device__ __forceinline__ void mma_16816(float* d, const uint32_t* a, const uint32_t* b) {
    asm volatile("mma.sync.aligned.m16n8k16.row.col.f32.bf16.bf16.f32 "
        "{%0,%1,%2,%3}, {%4,%5,%6,%7}, {%8,%9}, {%0,%1,%2,%3};"
        : "+f"(d[0]), "+f"(d[1]), "+f"(d[2]), "+f"(d[3])
        : "r"(a[0]), "r"(a[1]), "r"(a[2]), "r"(a[3]), "r"(b[0]), "r"(b[1]));
}
__device__ __forceinline__ void cp16(uint32_t dst, const void* src) {
    asm volatile("cp.async.cg.shared.global [%0], [%1], 16;" :: "r"(dst), "l"(src));
}
#define CP_COMMIT() asm volatile("cp.async.commit_group;" ::: "memory")
#define CP_WAIT(n)  asm volatile("cp.async.wait_group %0;" :: "n"(n) : "memory")

__device__ __forceinline__ float sig_(float x) { return 1.f / (1.f + expf(-x)); }

// SMEM tile geometry: 128 rows x 64 bf16, rows padded to 72 bf16 = 144 B
#define ROWB 144
#define TILEB 18432          // 128*144
#define BUFB  (4*TILEB)      // Ah, Al, Bh, Bl
#define GRU_SMEM (2*BUFB)    // double buffered = 147456 B

// ---------------------------------------------------------------------------
// init: split + transpose rk [K=1024][N=3072] -> rkT hi/lo [N=3072][K=1024]
// ---------------------------------------------------------------------------
__global__ __launch_bounds__(256) void k_rk_split(const float* __restrict__ rk)
{
    __shared__ float tile[32][33];
    const int n0 = blockIdx.x * 32, k0 = blockIdx.y * 32;
    const int tx = threadIdx.x & 31, ty = threadIdx.x >> 5;  // ty 0..7
#pragma unroll
    for (int i = 0; i < 4; i++)
        tile[ty + 8 * i][tx] = rk[(size_t)(k0 + ty + 8 * i) * G3 + n0 + tx];
    __syncthreads();
#pragma unroll
    for (int i = 0; i < 4; i++) {
        int n = n0 + ty + 8 * i;
        float v = tile[tx][ty + 8 * i];
        __nv_bfloat16 hi = __float2bfloat16(v);
        __nv_bfloat16 lo = __float2bfloat16(v - __bfloat162float(hi));
        g_rkT_hi[(size_t)n * Hh + k0 + tx] = hi;
        g_rkT_lo[(size_t)n * Hh + k0 + tx] = lo;
    }
}

// ---------------------------------------------------------------------------
// Kernel 1: xg = emb[tokens] @ gru_k + gru_bi   (fp32)
// ---------------------------------------------------------------------------
__global__ __launch_bounds__(256) void k_embed_gemm(
    const int* __restrict__ tokens, const float* __restrict__ emb,
    const float* __restrict__ gk, const float* __restrict__ bi)
{
    __shared__ float As[16][68];
    __shared__ float Bs[16][68];
    const int n0 = blockIdx.x * 64;
    const int m0 = blockIdx.y * 64;
    const int tid = threadIdx.x;
    const int tx = tid & 15, ty = tid >> 4;
    const int a_row = tid >> 2, a_c4 = tid & 3;
    const int b_row = tid >> 4, b_c4 = tid & 15;
    const int r = m0 + a_row;
    const int tok = tokens[(r & 127) * Tt + (r >> 7)];
    const float4* __restrict__ apt =
        reinterpret_cast<const float4*>(emb + (size_t)tok * Ee);

    float acc[4][4];
#pragma unroll
    for (int i = 0; i < 4; i++)
#pragma unroll
        for (int j = 0; j < 4; j++) acc[i][j] = 0.f;

    for (int k0 = 0; k0 < Ee; k0 += 16) {
        float4 av = apt[(k0 >> 2) + a_c4];
        float4 bv = *reinterpret_cast<const float4*>(
            gk + (size_t)(k0 + b_row) * G3 + n0 + b_c4 * 4);
        As[a_c4 * 4 + 0][a_row] = av.x;
        As[a_c4 * 4 + 1][a_row] = av.y;
        As[a_c4 * 4 + 2][a_row] = av.z;
        As[a_c4 * 4 + 3][a_row] = av.w;
        *reinterpret_cast<float4*>(&Bs[b_row][b_c4 * 4]) = bv;
        __syncthreads();
#pragma unroll
        for (int kk = 0; kk < 16; kk++) {
            float4 a = *reinterpret_cast<const float4*>(&As[kk][ty * 4]);
            float4 b = *reinterpret_cast<const float4*>(&Bs[kk][tx * 4]);
            float aa[4] = {a.x, a.y, a.z, a.w};
            float bb[4] = {b.x, b.y, b.z, b.w};
#pragma unroll
            for (int i = 0; i < 4; i++)
#pragma unroll
                for (int j = 0; j < 4; j++)
                    acc[i][j] = fmaf(aa[i], bb[j], acc[i][j]);
        }
        __syncthreads();
    }
#pragma unroll
    for (int i = 0; i < 4; i++) {
        int row = m0 + ty * 4 + i;
        float4 o;
        int col = n0 + tx * 4;
        o.x = acc[i][0] + bi[col + 0];
        o.y = acc[i][1] + bi[col + 1];
        o.z = acc[i][2] + bi[col + 2];
        o.w = acc[i][3] + bi[col + 3];
        *reinterpret_cast<float4*>(&g_xg[(size_t)row * G3 + col]) = o;
    }
}

// ---------------------------------------------------------------------------
// Kernel 2: persistent GRU with mma.sync bf16 (3-pass split, R4 pipeline).
// 144 CTAs = 24 n-tiles(128) x 6 k-splits (192,192,192,192,128,128).
// ---------------------------------------------------------------------------
__global__ __launch_bounds__(256, 1) void k_gru_mma(const float* __restrict__ br)
{
    extern __shared__ char smem[];
    const uint32_t sb = smem_to_u32(smem);
    const int tid = threadIdx.x;
    const int lane = tid & 31;
    const int wid = tid >> 5;
    const int ntile = blockIdx.x % NNT;
    const int ks    = blockIdx.x / NNT;      // 0..5
    const int n0    = ntile * 128;
    const int kbase = (ks < 4) ? ks * 192 : 768 + (ks - 4) * 128;
    const int nch   = (ks < 4) ? 3 : 2;      // chunks of 64 k
    const int mbase = (wid & 3) * 32;        // warp M rows (batch)
    const int nbase = (wid >> 2) * 64;       // warp N cols within tile

    // loader geometry
    const int lrow = tid >> 3;               // 0..31 (+32*i)
    const int lg   = tid & 7;                // 16B group
    // ldmatrix per-thread offsets
    const uint32_t aoff = (uint32_t)((lane & 15) * ROWB + ((lane >> 4) & 1) * 16);
    const uint32_t boff = (uint32_t)((((lane & 7) + ((lane >> 4) & 1) * 8)) * ROWB
                                     + ((lane >> 3) & 1) * 16);

    unsigned epoch = 0;

    for (int t = 0; t < Tt; t++) {
        if (t > 0) {
            // ---------------- phase A ----------------
            float accs[64];
#pragma unroll
            for (int i = 0; i < 64; i++) accs[i] = 0.f;

            // issue first two chunk loads
#pragma unroll
            for (int c = 0; c < 2; c++) {
                const int kcur = kbase + c * 64;
                const uint32_t base = sb + c * BUFB;
#pragma unroll
                for (int i = 0; i < 4; i++) {
                    const int row = lrow + 32 * i;
                    const uint32_t d = base + row * ROWB + lg * 16;
                    const size_t ea = ((size_t)row * Hh + kcur + lg * 8) * 2;
                    cp16(d,             (const char*)g_hhi + ea);
                    cp16(d + TILEB,     (const char*)g_hlo + ea);
                    const size_t eb = ((size_t)(n0 + row) * Hh + kcur + lg * 8) * 2;
                    cp16(d + 2 * TILEB, (const char*)g_rkT_hi + eb);
                    cp16(d + 3 * TILEB, (const char*)g_rkT_lo + eb);
                }
                CP_COMMIT();
            }

            for (int c = 0; c < nch; c++) {
                if (c < nch - 1) { CP_WAIT(1); } else { CP_WAIT(0); }
                __syncthreads();
                const uint32_t bufA = sb + (c & 1) * BUFB;
                // compute chunk c (4 k16 steps)
#pragma unroll
                for (int k = 0; k < 4; k++) {
                    uint32_t ah[2][4], al[2][4];
#pragma unroll
                    for (int mf = 0; mf < 2; mf++) {
                        const uint32_t ad = bufA + (mbase + mf * 16) * ROWB + k * 32 + aoff;
                        ldsm_x4(ah[mf], ad);
                        ldsm_x4(al[mf], ad + TILEB);
                    }
#pragma unroll
                    for (int nl = 0; nl < 4; nl++) {
                        const uint32_t bd = bufA + 2 * TILEB
                                          + (nbase + nl * 16) * ROWB + k * 32 + boff;
                        uint32_t bh[4], bl[4];
                        ldsm_x4(bh, bd);
                        ldsm_x4(bl, bd + TILEB);
#pragma unroll
                        for (int mf = 0; mf < 2; mf++) {
#pragma unroll
                            for (int h2 = 0; h2 < 2; h2++) {
                                float* a = &accs[(mf * 8 + nl * 2 + h2) * 4];
                                mma_16816(a, ah[mf], &bh[2 * h2]);
                                mma_16816(a, ah[mf], &bl[2 * h2]);
                                mma_16816(a, al[mf], &bh[2 * h2]);
                            }
                        }
                    }
                }
                __syncthreads();
                if (c + 2 < nch) {
                    // refill buffer (c&1) with chunk c+2
                    const int cc = c + 2;
                    const int kcur = kbase + cc * 64;
                    const uint32_t base = sb + (cc & 1) * BUFB;
#pragma unroll
                    for (int i = 0; i < 4; i++) {
                        const int row = lrow + 32 * i;
                        const uint32_t d = base + row * ROWB + lg * 16;
                        const size_t ea = ((size_t)row * Hh + kcur + lg * 8) * 2;
                        cp16(d,             (const char*)g_hhi + ea);
                        cp16(d + TILEB,     (const char*)g_hlo + ea);
                        const size_t eb = ((size_t)(n0 + row) * Hh + kcur + lg * 8) * 2;
                        cp16(d + 2 * TILEB, (const char*)g_rkT_hi + eb);
                        cp16(d + 3 * TILEB, (const char*)g_rkT_lo + eb);
                    }
                    CP_COMMIT();
                }
            }

            // epilogue: write partials [ks][b][j]
#pragma unroll
            for (int mf = 0; mf < 2; mf++) {
#pragma unroll
                for (int nf = 0; nf < 8; nf++) {
                    const float* a = &accs[(mf * 8 + nf) * 4];
                    const int row = mbase + mf * 16 + (lane >> 2);
                    const int col = n0 + nbase + (nf >> 1) * 16 + (nf & 1) * 8 + (lane & 3) * 2;
                    float* p = g_rgp + ((size_t)ks * Bb + row) * G3 + col;
                    *(float2*)p = make_float2(a[0], a[1]);
                    *(float2*)(p + (size_t)8 * G3) = make_float2(a[2], a[3]);
                }
            }
            // grid barrier
            __syncthreads();
            if (tid == 0) {
                __threadfence();
                epoch++;
                atomicAdd(&g_bar, 1u);
                while (*(volatile unsigned*)&g_bar < epoch * GRID_GRU) { }
            }
            __syncthreads();
        }

        // ---------------- phase B: gates ----------------
        {
            const float* __restrict__ xgt = g_xg + (size_t)t * Bb * G3;
            const float* __restrict__ hprev = g_hs + (size_t)(t - 1) * Bb * Hh;
            float* __restrict__ hcur = g_hs + (size_t)t * Bb * Hh;
            for (int v = blockIdx.x * 256 + tid; v < (Bb * Hh) / 4; v += GRID_GRU * 256) {
                const int b = v >> 8;
                const int j = (v & 255) << 2;
                const size_t xb = (size_t)b * G3 + j;
                float4 xz = *(const float4*)(xgt + xb);
                float4 xr = *(const float4*)(xgt + xb + Hh);
                float4 xh = *(const float4*)(xgt + xb + 2 * Hh);
                float4 az = make_float4(0.f, 0.f, 0.f, 0.f);
                float4 ar = az, ah = az, hp = az;
                if (t > 0) {
#pragma unroll
                    for (int s = 0; s < NKS; s++) {
                        const float* rp = g_rgp + (size_t)s * Bb * G3 + xb;
                        float4 a0 = __ldcg((const float4*)(rp));
                        float4 a1 = __ldcg((const float4*)(rp + Hh));
                        float4 a2 = __ldcg((const float4*)(rp + 2 * Hh));
                        az.x += a0.x; az.y += a0.y; az.z += a0.z; az.w += a0.w;
                        ar.x += a1.x; ar.y += a1.y; ar.z += a1.z; ar.w += a1.w;
                        ah.x += a2.x; ah.y += a2.y; ah.z += a2.z; ah.w += a2.w;
                    }
                    hp = __ldcg((const float4*)(hprev + (size_t)b * Hh + j));
                }
                float4 bz = *(const float4*)(br + j);
                float4 brv = *(const float4*)(br + Hh + j);
                float4 bh = *(const float4*)(br + 2 * Hh + j);
                float4 o;
#define GATE1(C) { \
                float z = sig_(xz.C + az.C + bz.C); \
                float rg = sig_(xr.C + ar.C + brv.C); \
                float th = tanhf(xh.C + rg * (ah.C + bh.C)); \
                o.C = z * hp.C + (1.f - z) * th; }
                GATE1(x) GATE1(y) GATE1(z) GATE1(w)
#undef GATE1
                *(float4*)(hcur + (size_t)b * Hh + j) = o;
                __nv_bfloat16 h0 = __float2bfloat16(o.x);
                __nv_bfloat16 h1 = __float2bfloat16(o.y);
                __nv_bfloat16 h2 = __float2bfloat16(o.z);
                __nv_bfloat16 h3 = __float2bfloat16(o.w);
                union { __nv_bfloat16 bf[4]; uint2 u; } ph, pl;
                ph.bf[0] = h0; ph.bf[1] = h1; ph.bf[2] = h2; ph.bf[3] = h3;
                pl.bf[0] = __float2bfloat16(o.x - __bfloat162float(h0));
                pl.bf[1] = __float2bfloat16(o.y - __bfloat162float(h1));
                pl.bf[2] = __float2bfloat16(o.z - __bfloat162float(h2));
                pl.bf[3] = __float2bfloat16(o.w - __bfloat162float(h3));
                *(uint2*)(g_hhi + (size_t)b * Hh + j) = ph.u;
                *(uint2*)(g_hlo + (size_t)b * Hh + j) = pl.u;
            }
        }
        // grid barrier
        __syncthreads();
        if (tid == 0) {
            __threadfence();
            epoch++;
            atomicAdd(&g_bar, 1u);
            while (*(volatile unsigned*)&g_bar < epoch * GRID_GRU) { }
        }
        __syncthreads();
    }
}

// ---------------------------------------------------------------------------
// Kernel 3: d = relu(hs @ w1 + b1)
// ---------------------------------------------------------------------------
__global__ __launch_bounds__(256) void k_w1relu(
    const float* __restrict__ w1, const float* __restrict__ b1)
{
    __shared__ float As[16][68];
    __shared__ float Bs[16][68];
    const int n0 = blockIdx.x * 64;
    const int m0 = blockIdx.y * 64;
    const int tid = threadIdx.x;
    const int tx = tid & 15, ty = tid >> 4;
    const int a_row = tid >> 2, a_c4 = tid & 3;
    const int b_row = tid >> 4, b_c4 = tid & 15;
    const float* __restrict__ apt = g_hs + (size_t)(m0 + a_row) * Hh;

    float acc[4][4];
#pragma unroll
    for (int i = 0; i < 4; i++)
#pragma unroll
        for (int j = 0; j < 4; j++) acc[i][j] = 0.f;

    for (int k0 = 0; k0 < Hh; k0 += 16) {
        float4 av = *reinterpret_cast<const float4*>(apt + k0 + a_c4 * 4);
        float4 bv = *reinterpret_cast<const float4*>(
            w1 + (size_t)(k0 + b_row) * Dd + n0 + b_c4 * 4);
        As[a_c4 * 4 + 0][a_row] = av.x;
        As[a_c4 * 4 + 1][a_row] = av.y;
        As[a_c4 * 4 + 2][a_row] = av.z;
        As[a_c4 * 4 + 3][a_row] = av.w;
        *reinterpret_cast<float4*>(&Bs[b_row][b_c4 * 4]) = bv;
        __syncthreads();
#pragma unroll
        for (int kk = 0; kk < 16; kk++) {
            float4 a = *reinterpret_cast<const float4*>(&As[kk][ty * 4]);
            float4 b = *reinterpret_cast<const float4*>(&Bs[kk][tx * 4]);
            float aa[4] = {a.x, a.y, a.z, a.w};
            float bb[4] = {b.x, b.y, b.z, b.w};
#pragma unroll
            for (int i = 0; i < 4; i++)
#pragma unroll
                for (int j = 0; j < 4; j++)
                    acc[i][j] = fmaf(aa[i], bb[j], acc[i][j]);
        }
        __syncthreads();
    }
#pragma unroll
    for (int i = 0; i < 4; i++) {
        int row = m0 + ty * 4 + i;
        int col = n0 + tx * 4;
        float4 o;
        o.x = fmaxf(acc[i][0] + b1[col + 0], 0.f);
        o.y = fmaxf(acc[i][1] + b1[col + 1], 0.f);
        o.z = fmaxf(acc[i][2] + b1[col + 2], 0.f);
        o.w = fmaxf(acc[i][3] + b1[col + 3], 0.f);
        *reinterpret_cast<float4*>(&g_d[(size_t)row * Dd + col]) = o;
    }
}

// ---------------------------------------------------------------------------
// Kernel 4: logits = d @ w2 + b2 -> d_out as [B][T][V]
// ---------------------------------------------------------------------------
__global__ __launch_bounds__(256) void k_w2(
    const float* __restrict__ w2, const float* __restrict__ b2,
    float* __restrict__ out)
{
    __shared__ float As[16][68];
    __shared__ float Bs[16][68];
    const int n0 = blockIdx.x * 64;
    const int m0 = blockIdx.y * 64;
    const int tid = threadIdx.x;
    const int tx = tid & 15, ty = tid >> 4;
    const int a_row = tid >> 2, a_c4 = tid & 3;
    const int b_row = tid >> 4, b_c4 = tid & 15;
    const float* __restrict__ apt = g_d + (size_t)(m0 + a_row) * Dd;
    const bool full = (n0 + 64 <= Vv);

    float acc[4][4];
#pragma unroll
    for (int i = 0; i < 4; i++)
#pragma unroll
        for (int j = 0; j < 4; j++) acc[i][j] = 0.f;

    for (int k0 = 0; k0 < Dd; k0 += 16) {
        float4 av = *reinterpret_cast<const float4*>(apt + k0 + a_c4 * 4);
        As[a_c4 * 4 + 0][a_row] = av.x;
        As[a_c4 * 4 + 1][a_row] = av.y;
        As[a_c4 * 4 + 2][a_row] = av.z;
        As[a_c4 * 4 + 3][a_row] = av.w;
        if (full) {
            float4 bv = *reinterpret_cast<const float4*>(
                w2 + (size_t)(k0 + b_row) * Vv + n0 + b_c4 * 4);
            *reinterpret_cast<float4*>(&Bs[b_row][b_c4 * 4]) = bv;
        } else {
#pragma unroll
            for (int c = 0; c < 4; c++) {
                int col = n0 + b_c4 * 4 + c;
                Bs[b_row][b_c4 * 4 + c] =
                    (col < Vv) ? w2[(size_t)(k0 + b_row) * Vv + col] : 0.f;
            }
        }
        __syncthreads();
#pragma unroll
        for (int kk = 0; kk < 16; kk++) {
            float4 a = *reinterpret_cast<const float4*>(&As[kk][ty * 4]);
            float4 b = *reinterpret_cast<const float4*>(&Bs[kk][tx * 4]);
            float aa[4] = {a.x, a.y, a.z, a.w};
            float bb[4] = {b.x, b.y, b.z, b.w};
#pragma unroll
            for (int i = 0; i < 4; i++)
#pragma unroll
                for (int j = 0; j < 4; j++)
                    acc[i][j] = fmaf(aa[i], bb[j], acc[i][j]);
        }
        __syncthreads();
    }
#pragma unroll
    for (int i = 0; i < 4; i++) {
        int rr = m0 + ty * 4 + i;
        int t = rr >> 7, b = rr & 127;
        size_t obase = ((size_t)b * Tt + t) * Vv;
#pragma unroll
        for (int j = 0; j < 4; j++) {
            int col = n0 + tx * 4 + j;
            if (col < Vv) out[obase + col] = acc[i][j] + b2[col];
        }
    }
}

// ---------------------------------------------------------------------------
// Kernel 5: softmax rows of 10000 with logits*50
// ---------------------------------------------------------------------------
__global__ __launch_bounds__(256) void k_softmax(float* __restrict__ out)
{
    float* __restrict__ p = out + (size_t)blockIdx.x * Vv;
    const int tid = threadIdx.x;
    float vals[40];
    float mx = -1e30f;
#pragma unroll
    for (int i = 0; i < 40; i++) {
        int idx = tid + (i << 8);
        if (idx < Vv) {
            float v = p[idx] * 50.0f;
            vals[i] = v;
            mx = fmaxf(mx, v);
        } else {
            vals[i] = -1e30f;
        }
    }
    __shared__ float redm[8];
    __shared__ float reds[8];
#pragma unroll
    for (int o = 16; o; o >>= 1) mx = fmaxf(mx, __shfl_xor_sync(0xffffffffu, mx, o));
    if ((tid & 31) == 0) redm[tid >> 5] = mx;
    __syncthreads();
    mx = redm[0];
#pragma unroll
    for (int w = 1; w < 8; w++) mx = fmaxf(mx, redm[w]);

    float s = 0.f;
#pragma unroll
    for (int i = 0; i < 40; i++) {
        int idx = tid + (i << 8);
        if (idx < Vv) {
            float e = expf(vals[i] - mx);
            vals[i] = e;
            s += e;
        }
    }
#pragma unroll
    for (int o = 16; o; o >>= 1) s += __shfl_xor_sync(0xffffffffu, s, o);
    if ((tid & 31) == 0) reds[tid >> 5] = s;
    __syncthreads();
    float tot = 0.f;
#pragma unroll
    for (int w = 0; w < 8; w++) tot += reds[w];
    float inv = 1.0f / tot;
#pragma unroll
    for (int i = 0; i < 40; i++) {
        int idx = tid + (i << 8);
        if (idx < Vv) p[idx] = vals[i] * inv;
    }
}

// ---------------------------------------------------------------------------
extern "C" void kernel_launch(void* const* d_in, const int* in_sizes, int n_in,
                              void* d_out, int out_size)
{
    const int*   tokens = (const int*)  d_in[0];
    const float* emb    = (const float*)d_in[1];
    const float* gk     = (const float*)d_in[2];
    const float* grk    = (const float*)d_in[3];
    const float* gbi    = (const float*)d_in[4];
    const float* gbr    = (const float*)d_in[5];
    const float* w1     = (const float*)d_in[6];
    const float* b1     = (const float*)d_in[7];
    const float* w2     = (const float*)d_in[8];
    const float* b2     = (const float*)d_in[9];
    float* out = (float*)d_out;

    cudaFuncSetAttribute(k_gru_mma, cudaFuncAttributeMaxDynamicSharedMemorySize, GRU_SMEM);

    dim3 blk(256);
    k_reset<<<1, 1>>>();
    k_rk_split<<<dim3(G3 / 32, Hh / 32), blk>>>(grk);
    k_embed_gemm<<<dim3(G3 / 64, MROWS / 64), blk>>>(tokens, emb, gk, gbi);
    k_gru_mma<<<GRID_GRU, blk, GRU_SMEM>>>(gbr);
    k_w1relu<<<dim3(Dd / 64, MROWS / 64), blk>>>(w1, b1);
    k_w2<<<dim3((Vv + 63) / 64, MROWS / 64), blk>>>(w2, b2, out);
    k_softmax<<<MROWS, blk>>>(out);
}

// round 11
// speedup vs baseline: 3.4486x; 1.1802x over previous
#include <cuda_runtime.h>
#include <cuda_bf16.h>
#include <math.h>
#include <stdint.h>

#define Bb 128
#define Tt 128
#define Vv 10000
#define VvPad 10112          // 79*128
#define Ee 256
#define Hh 1024
#define Dd 128
#define G3 3072              // 3*H
#define MROWS (Bb*Tt)        // 16384
#define NKS 6                // GRU k-splits: 192,192,192,192,128,128
#define NNT 24               // GRU n-tiles of 128
#define GRID_GRU (NKS*NNT)   // 144 CTAs, all co-resident

// ---------------- scratch (__device__ globals: allowed) --------------------
__device__ float g_xg[MROWS * G3];       // [T][B][3H] input-side preacts (incl bi)
__device__ float g_hs[MROWS * Hh];       // [T][B][H]
__device__ float g_rgp[NKS * Bb * G3];   // recurrent matmul partials per k-split
__device__ __nv_bfloat16 g_rkT_hi[G3 * Hh];  // rk^T split hi  [n][k]
__device__ __nv_bfloat16 g_rkT_lo[G3 * Hh];  // rk^T split lo
__device__ __nv_bfloat16 g_hhi[Bb * Hh];     // h_t split hi [b][k]
__device__ __nv_bfloat16 g_hlo[Bb * Hh];     // h_t split lo
__device__ __nv_bfloat16 g_w2T_hi[VvPad * Dd]; // w2^T split, zero-padded rows
__device__ __nv_bfloat16 g_w2T_lo[VvPad * Dd];
__device__ __nv_bfloat16 g_dhi[MROWS * Dd];  // d = relu(hs@w1+b1) split hi
__device__ __nv_bfloat16 g_dlo[MROWS * Dd];  // split lo
__device__ unsigned g_bar;

__global__ void k_reset() { g_bar = 0u; }

// ---------------- PTX helpers ----------------------------------------------
__device__ __forceinline__ uint32_t smem_to_u32(const void* p) {
    uint32_t a;
    asm("{ .reg .u64 t; cvta.to.shared.u64 t, %1; cvt.u32.u64 %0, t; }"
        : "=r"(a) : "l"(p));
    return a;
}
__device__ __forceinline__ void ldsm_x4(uint32_t* r, uint32_t addr) {
    asm volatile("ldmatrix.sync.aligned.m8n8.x4.shared.b16 {%0,%1,%2,%3}, [%4];"
        : "=r"(r[0]), "=r"(r[1]), "=r"(r[2]), "=r"(r[3]) : "r"(addr));
}
__device__ __forceinline__ void mma_16816(float* d, const uint32_t* a, const uint32_t* b) {
    asm volatile("mma.sync.aligned.m16n8k16.row.col.f32.bf16.bf16.f32 "
        "{%0,%1,%2,%3}, {%4,%5,%6,%7}, {%8,%9}, {%0,%1,%2,%3};"
        : "+f"(d[0]), "+f"(d[1]), "+f"(d[2]), "+f"(d[3])
        : "r"(a[0]), "r"(a[1]), "r"(a[2]), "r"(a[3]), "r"(b[0]), "r"(b[1]));
}
__device__ __forceinline__ void cp16(uint32_t dst, const void* src) {
    asm volatile("cp.async.cg.shared.global [%0], [%1], 16;" :: "r"(dst), "l"(src));
}
#define CP_COMMIT() asm volatile("cp.async.commit_group;" ::: "memory")
#define CP_WAIT(n)  asm volatile("cp.async.wait_group %0;" :: "n"(n) : "memory")

__device__ __forceinline__ float sig_(float x) { return 1.f / (1.f + expf(-x)); }

// SMEM tile geometry: 128 rows x 64 bf16, rows padded to 72 bf16 = 144 B
#define ROWB 144
#define TILEB 18432          // 128*144
#define BUFB  (4*TILEB)      // Ah, Al, Bh, Bl
#define GRU_SMEM (2*BUFB)    // double buffered = 147456 B

// ---------------------------------------------------------------------------
// init: split + transpose rk [K=1024][N=3072] -> rkT hi/lo [N=3072][K=1024]
// ---------------------------------------------------------------------------
__global__ __launch_bounds__(256) void k_rk_split(const float* __restrict__ rk)
{
    __shared__ float tile[32][33];
    const int n0 = blockIdx.x * 32, k0 = blockIdx.y * 32;
    const int tx = threadIdx.x & 31, ty = threadIdx.x >> 5;  // ty 0..7
#pragma unroll
    for (int i = 0; i < 4; i++)
        tile[ty + 8 * i][tx] = rk[(size_t)(k0 + ty + 8 * i) * G3 + n0 + tx];
    __syncthreads();
#pragma unroll
    for (int i = 0; i < 4; i++) {
        int n = n0 + ty + 8 * i;
        float v = tile[tx][ty + 8 * i];
        __nv_bfloat16 hi = __float2bfloat16(v);
        __nv_bfloat16 lo = __float2bfloat16(v - __bfloat162float(hi));
        g_rkT_hi[(size_t)n * Hh + k0 + tx] = hi;
        g_rkT_lo[(size_t)n * Hh + k0 + tx] = lo;
    }
}

// ---------------------------------------------------------------------------
// init: split + transpose w2 [Dd=128][Vv] -> w2T hi/lo [VvPad][Dd], zero-pad
// grid (VvPad/32, Dd/32)
// ---------------------------------------------------------------------------
__global__ __launch_bounds__(256) void k_w2split(const float* __restrict__ w2)
{
    __shared__ float tile[32][33];
    const int n0 = blockIdx.x * 32, k0 = blockIdx.y * 32;
    const int tx = threadIdx.x & 31, ty = threadIdx.x >> 5;
#pragma unroll
    for (int i = 0; i < 4; i++) {
        int c = n0 + tx;
        tile[ty + 8 * i][tx] =
            (c < Vv) ? w2[(size_t)(k0 + ty + 8 * i) * Vv + c] : 0.f;
    }
    __syncthreads();
#pragma unroll
    for (int i = 0; i < 4; i++) {
        int n = n0 + ty + 8 * i;
        float v = tile[tx][ty + 8 * i];
        __nv_bfloat16 hi = __float2bfloat16(v);
        __nv_bfloat16 lo = __float2bfloat16(v - __bfloat162float(hi));
        g_w2T_hi[(size_t)n * Dd + k0 + tx] = hi;
        g_w2T_lo[(size_t)n * Dd + k0 + tx] = lo;
    }
}

// ---------------------------------------------------------------------------
// Kernel 1: xg = emb[tokens] @ gru_k + gru_bi   (fp32, R7 unchanged)
// ---------------------------------------------------------------------------
__global__ __launch_bounds__(256) void k_embed_gemm(
    const int* __restrict__ tokens, const float* __restrict__ emb,
    const float* __restrict__ gk, const float* __restrict__ bi)
{
    __shared__ float As[16][68];
    __shared__ float Bs[16][68];
    const int n0 = blockIdx.x * 64;
    const int m0 = blockIdx.y * 64;
    const int tid = threadIdx.x;
    const int tx = tid & 15, ty = tid >> 4;
    const int a_row = tid >> 2, a_c4 = tid & 3;
    const int b_row = tid >> 4, b_c4 = tid & 15;
    const int r = m0 + a_row;
    const int tok = tokens[(r & 127) * Tt + (r >> 7)];
    const float4* __restrict__ apt =
        reinterpret_cast<const float4*>(emb + (size_t)tok * Ee);

    float acc[4][4];
#pragma unroll
    for (int i = 0; i < 4; i++)
#pragma unroll
        for (int j = 0; j < 4; j++) acc[i][j] = 0.f;

    for (int k0 = 0; k0 < Ee; k0 += 16) {
        float4 av = apt[(k0 >> 2) + a_c4];
        float4 bv = *reinterpret_cast<const float4*>(
            gk + (size_t)(k0 + b_row) * G3 + n0 + b_c4 * 4);
        As[a_c4 * 4 + 0][a_row] = av.x;
        As[a_c4 * 4 + 1][a_row] = av.y;
        As[a_c4 * 4 + 2][a_row] = av.z;
        As[a_c4 * 4 + 3][a_row] = av.w;
        *reinterpret_cast<float4*>(&Bs[b_row][b_c4 * 4]) = bv;
        __syncthreads();
#pragma unroll
        for (int kk = 0; kk < 16; kk++) {
            float4 a = *reinterpret_cast<const float4*>(&As[kk][ty * 4]);
            float4 b = *reinterpret_cast<const float4*>(&Bs[kk][tx * 4]);
            float aa[4] = {a.x, a.y, a.z, a.w};
            float bb[4] = {b.x, b.y, b.z, b.w};
#pragma unroll
            for (int i = 0; i < 4; i++)
#pragma unroll
                for (int j = 0; j < 4; j++)
                    acc[i][j] = fmaf(aa[i], bb[j], acc[i][j]);
        }
        __syncthreads();
    }
#pragma unroll
    for (int i = 0; i < 4; i++) {
        int row = m0 + ty * 4 + i;
        float4 o;
        int col = n0 + tx * 4;
        o.x = acc[i][0] + bi[col + 0];
        o.y = acc[i][1] + bi[col + 1];
        o.z = acc[i][2] + bi[col + 2];
        o.w = acc[i][3] + bi[col + 3];
        *reinterpret_cast<float4*>(&g_xg[(size_t)row * G3 + col]) = o;
    }
}

// ---------------------------------------------------------------------------
// Kernel 2: persistent GRU with mma.sync bf16 (R7 verbatim).
// 144 CTAs = 24 n-tiles(128) x 6 k-splits (192,192,192,192,128,128).
// ---------------------------------------------------------------------------
__global__ __launch_bounds__(256, 1) void k_gru_mma(const float* __restrict__ br)
{
    extern __shared__ char smem[];
    const uint32_t sb = smem_to_u32(smem);
    const int tid = threadIdx.x;
    const int lane = tid & 31;
    const int wid = tid >> 5;
    const int ntile = blockIdx.x % NNT;
    const int ks    = blockIdx.x / NNT;      // 0..5
    const int n0    = ntile * 128;
    const int kbase = (ks < 4) ? ks * 192 : 768 + (ks - 4) * 128;
    const int nch   = (ks < 4) ? 3 : 2;      // chunks of 64 k
    const int mbase = (wid & 3) * 32;        // warp M rows (batch)
    const int nbase = (wid >> 2) * 64;       // warp N cols within tile

    // loader geometry
    const int lrow = tid >> 3;               // 0..31 (+32*i)
    const int lg   = tid & 7;                // 16B group
    // ldmatrix per-thread offsets
    const uint32_t aoff = (uint32_t)((lane & 15) * ROWB + ((lane >> 4) & 1) * 16);
    const uint32_t boff = (uint32_t)((((lane & 7) + ((lane >> 4) & 1) * 8)) * ROWB
                                     + ((lane >> 3) & 1) * 16);

    unsigned epoch = 0;

    for (int t = 0; t < Tt; t++) {
        if (t > 0) {
            // ---------------- phase A ----------------
            float accs[64];
#pragma unroll
            for (int i = 0; i < 64; i++) accs[i] = 0.f;

            // issue first two chunk loads
#pragma unroll
            for (int c = 0; c < 2; c++) {
                const int kcur = kbase + c * 64;
                const uint32_t base = sb + c * BUFB;
#pragma unroll
                for (int i = 0; i < 4; i++) {
                    const int row = lrow + 32 * i;
                    const uint32_t d = base + row * ROWB + lg * 16;
                    const size_t ea = ((size_t)row * Hh + kcur + lg * 8) * 2;
                    cp16(d,             (const char*)g_hhi + ea);
                    cp16(d + TILEB,     (const char*)g_hlo + ea);
                    const size_t eb = ((size_t)(n0 + row) * Hh + kcur + lg * 8) * 2;
                    cp16(d + 2 * TILEB, (const char*)g_rkT_hi + eb);
                    cp16(d + 3 * TILEB, (const char*)g_rkT_lo + eb);
                }
                CP_COMMIT();
            }

            for (int c = 0; c < nch; c++) {
                if (c < nch - 1) { CP_WAIT(1); } else { CP_WAIT(0); }
                __syncthreads();
                const uint32_t bufA = sb + (c & 1) * BUFB;
                // compute chunk c (4 k16 steps)
#pragma unroll
                for (int k = 0; k < 4; k++) {
                    uint32_t ah[2][4], al[2][4];
#pragma unroll
                    for (int mf = 0; mf < 2; mf++) {
                        const uint32_t ad = bufA + (mbase + mf * 16) * ROWB + k * 32 + aoff;
                        ldsm_x4(ah[mf], ad);
                        ldsm_x4(al[mf], ad + TILEB);
                    }
#pragma unroll
                    for (int nl = 0; nl < 4; nl++) {
                        const uint32_t bd = bufA + 2 * TILEB
                                          + (nbase + nl * 16) * ROWB + k * 32 + boff;
                        uint32_t bh[4], bl[4];
                        ldsm_x4(bh, bd);
                        ldsm_x4(bl, bd + TILEB);
#pragma unroll
                        for (int mf = 0; mf < 2; mf++) {
#pragma unroll
                            for (int h2 = 0; h2 < 2; h2++) {
                                float* a = &accs[(mf * 8 + nl * 2 + h2) * 4];
                                mma_16816(a, ah[mf], &bh[2 * h2]);
                                mma_16816(a, ah[mf], &bl[2 * h2]);
                                mma_16816(a, al[mf], &bh[2 * h2]);
                            }
                        }
                    }
                }
                __syncthreads();
                if (c + 2 < nch) {
                    // refill buffer (c&1) with chunk c+2
                    const int cc = c + 2;
                    const int kcur = kbase + cc * 64;
                    const uint32_t base = sb + (cc & 1) * BUFB;
#pragma unroll
                    for (int i = 0; i < 4; i++) {
                        const int row = lrow + 32 * i;
                        const uint32_t d = base + row * ROWB + lg * 16;
                        const size_t ea = ((size_t)row * Hh + kcur + lg * 8) * 2;
                        cp16(d,             (const char*)g_hhi + ea);
                        cp16(d + TILEB,     (const char*)g_hlo + ea);
                        const size_t eb = ((size_t)(n0 + row) * Hh + kcur + lg * 8) * 2;
                        cp16(d + 2 * TILEB, (const char*)g_rkT_hi + eb);
                        cp16(d + 3 * TILEB, (const char*)g_rkT_lo + eb);
                    }
                    CP_COMMIT();
                }
            }

            // epilogue: write partials [ks][b][j]
#pragma unroll
            for (int mf = 0; mf < 2; mf++) {
#pragma unroll
                for (int nf = 0; nf < 8; nf++) {
                    const float* a = &accs[(mf * 8 + nf) * 4];
                    const int row = mbase + mf * 16 + (lane >> 2);
                    const int col = n0 + nbase + (nf >> 1) * 16 + (nf & 1) * 8 + (lane & 3) * 2;
                    float* p = g_rgp + ((size_t)ks * Bb + row) * G3 + col;
                    *(float2*)p = make_float2(a[0], a[1]);
                    *(float2*)(p + (size_t)8 * G3) = make_float2(a[2], a[3]);
                }
            }
            // grid barrier
            __syncthreads();
            if (tid == 0) {
                __threadfence();
                epoch++;
                atomicAdd(&g_bar, 1u);
                while (*(volatile unsigned*)&g_bar < epoch * GRID_GRU) { }
            }
            __syncthreads();
        }

        // ---------------- phase B: gates ----------------
        {
            const float* __restrict__ xgt = g_xg + (size_t)t * Bb * G3;
            const float* __restrict__ hprev = g_hs + (size_t)(t - 1) * Bb * Hh;
            float* __restrict__ hcur = g_hs + (size_t)t * Bb * Hh;
            for (int v = blockIdx.x * 256 + tid; v < (Bb * Hh) / 4; v += GRID_GRU * 256) {
                const int b = v >> 8;
                const int j = (v & 255) << 2;
                const size_t xb = (size_t)b * G3 + j;
                float4 xz = *(const float4*)(xgt + xb);
                float4 xr = *(const float4*)(xgt + xb + Hh);
                float4 xh = *(const float4*)(xgt + xb + 2 * Hh);
                float4 az = make_float4(0.f, 0.f, 0.f, 0.f);
                float4 ar = az, ah = az, hp = az;
                if (t > 0) {
#pragma unroll
                    for (int s = 0; s < NKS; s++) {
                        const float* rp = g_rgp + (size_t)s * Bb * G3 + xb;
                        float4 a0 = __ldcg((const float4*)(rp));
                        float4 a1 = __ldcg((const float4*)(rp + Hh));
                        float4 a2 = __ldcg((const float4*)(rp + 2 * Hh));
                        az.x += a0.x; az.y += a0.y; az.z += a0.z; az.w += a0.w;
                        ar.x += a1.x; ar.y += a1.y; ar.z += a1.z; ar.w += a1.w;
                        ah.x += a2.x; ah.y += a2.y; ah.z += a2.z; ah.w += a2.w;
                    }
                    hp = __ldcg((const float4*)(hprev + (size_t)b * Hh + j));
                }
                float4 bz = *(const float4*)(br + j);
                float4 brv = *(const float4*)(br + Hh + j);
                float4 bh = *(const float4*)(br + 2 * Hh + j);
                float4 o;
#define GATE1(C) { \
                float z = sig_(xz.C + az.C + bz.C); \
                float rg = sig_(xr.C + ar.C + brv.C); \
                float th = tanhf(xh.C + rg * (ah.C + bh.C)); \
                o.C = z * hp.C + (1.f - z) * th; }
                GATE1(x) GATE1(y) GATE1(z) GATE1(w)
#undef GATE1
                *(float4*)(hcur + (size_t)b * Hh + j) = o;
                __nv_bfloat16 h0 = __float2bfloat16(o.x);
                __nv_bfloat16 h1 = __float2bfloat16(o.y);
                __nv_bfloat16 h2 = __float2bfloat16(o.z);
                __nv_bfloat16 h3 = __float2bfloat16(o.w);
                union { __nv_bfloat16 bf[4]; uint2 u; } ph, pl;
                ph.bf[0] = h0; ph.bf[1] = h1; ph.bf[2] = h2; ph.bf[3] = h3;
                pl.bf[0] = __float2bfloat16(o.x - __bfloat162float(h0));
                pl.bf[1] = __float2bfloat16(o.y - __bfloat162float(h1));
                pl.bf[2] = __float2bfloat16(o.z - __bfloat162float(h2));
                pl.bf[3] = __float2bfloat16(o.w - __bfloat162float(h3));
                *(uint2*)(g_hhi + (size_t)b * Hh + j) = ph.u;
                *(uint2*)(g_hlo + (size_t)b * Hh + j) = pl.u;
            }
        }
        // grid barrier
        __syncthreads();
        if (tid == 0) {
            __threadfence();
            epoch++;
            atomicAdd(&g_bar, 1u);
            while (*(volatile unsigned*)&g_bar < epoch * GRID_GRU) { }
        }
        __syncthreads();
    }
}

// ---------------------------------------------------------------------------
// Kernel 3: d = relu(hs @ w1 + b1)  (fp32, R7) + emit bf16 hi/lo split
// ---------------------------------------------------------------------------
__global__ __launch_bounds__(256) void k_w1relu(
    const float* __restrict__ w1, const float* __restrict__ b1)
{
    __shared__ float As[16][68];
    __shared__ float Bs[16][68];
    const int n0 = blockIdx.x * 64;
    const int m0 = blockIdx.y * 64;
    const int tid = threadIdx.x;
    const int tx = tid & 15, ty = tid >> 4;
    const int a_row = tid >> 2, a_c4 = tid & 3;
    const int b_row = tid >> 4, b_c4 = tid & 15;
    const float* __restrict__ apt = g_hs + (size_t)(m0 + a_row) * Hh;

    float acc[4][4];
#pragma unroll
    for (int i = 0; i < 4; i++)
#pragma unroll
        for (int j = 0; j < 4; j++) acc[i][j] = 0.f;

    for (int k0 = 0; k0 < Hh; k0 += 16) {
        float4 av = *reinterpret_cast<const float4*>(apt + k0 + a_c4 * 4);
        float4 bv = *reinterpret_cast<const float4*>(
            w1 + (size_t)(k0 + b_row) * Dd + n0 + b_c4 * 4);
        As[a_c4 * 4 + 0][a_row] = av.x;
        As[a_c4 * 4 + 1][a_row] = av.y;
        As[a_c4 * 4 + 2][a_row] = av.z;
        As[a_c4 * 4 + 3][a_row] = av.w;
        *reinterpret_cast<float4*>(&Bs[b_row][b_c4 * 4]) = bv;
        __syncthreads();
#pragma unroll
        for (int kk = 0; kk < 16; kk++) {
            float4 a = *reinterpret_cast<const float4*>(&As[kk][ty * 4]);
            float4 b = *reinterpret_cast<const float4*>(&Bs[kk][tx * 4]);
            float aa[4] = {a.x, a.y, a.z, a.w};
            float bb[4] = {b.x, b.y, b.z, b.w};
#pragma unroll
            for (int i = 0; i < 4; i++)
#pragma unroll
                for (int j = 0; j < 4; j++)
                    acc[i][j] = fmaf(aa[i], bb[j], acc[i][j]);
        }
        __syncthreads();
    }
#pragma unroll
    for (int i = 0; i < 4; i++) {
        int row = m0 + ty * 4 + i;
        int col = n0 + tx * 4;
        float4 o;
        o.x = fmaxf(acc[i][0] + b1[col + 0], 0.f);
        o.y = fmaxf(acc[i][1] + b1[col + 1], 0.f);
        o.z = fmaxf(acc[i][2] + b1[col + 2], 0.f);
        o.w = fmaxf(acc[i][3] + b1[col + 3], 0.f);
        union { __nv_bfloat16 bf[4]; uint2 u; } ph, pl;
        ph.bf[0] = __float2bfloat16(o.x);
        ph.bf[1] = __float2bfloat16(o.y);
        ph.bf[2] = __float2bfloat16(o.z);
        ph.bf[3] = __float2bfloat16(o.w);
        pl.bf[0] = __float2bfloat16(o.x - __bfloat162float(ph.bf[0]));
        pl.bf[1] = __float2bfloat16(o.y - __bfloat162float(ph.bf[1]));
        pl.bf[2] = __float2bfloat16(o.z - __bfloat162float(ph.bf[2]));
        pl.bf[3] = __float2bfloat16(o.w - __bfloat162float(ph.bf[3]));
        *(uint2*)(g_dhi + (size_t)row * Dd + col) = ph.u;
        *(uint2*)(g_dlo + (size_t)row * Dd + col) = pl.u;
    }
}

// ---------------------------------------------------------------------------
// Kernel 4: logits = d @ w2 + b2 -> out [B][T][V]  (3-pass split mma)
// grid (79 n-tiles, 128 m-tiles).  Pipeline copied from k_gru_mma phase A.
// ---------------------------------------------------------------------------
__global__ __launch_bounds__(256, 1) void k_w2_mma(
    const float* __restrict__ b2, float* __restrict__ out)
{
    extern __shared__ char smem[];
    const uint32_t sb = smem_to_u32(smem);
    const int tid = threadIdx.x;
    const int lane = tid & 31;
    const int wid = tid >> 5;
    const int m0 = blockIdx.y * 128;
    const int n0 = blockIdx.x * 128;
    const int mbase = (wid & 3) * 32;
    const int nbase = (wid >> 2) * 64;
    const int lrow = tid >> 3;
    const int lg   = tid & 7;
    const uint32_t aoff = (uint32_t)((lane & 15) * ROWB + ((lane >> 4) & 1) * 16);
    const uint32_t boff = (uint32_t)((((lane & 7) + ((lane >> 4) & 1) * 8)) * ROWB
                                     + ((lane >> 3) & 1) * 16);

    float accs[64];
#pragma unroll
    for (int i = 0; i < 64; i++) accs[i] = 0.f;

    // preload both k-chunks (Dd = 128 = 2 chunks of 64)
#pragma unroll
    for (int c = 0; c < 2; c++) {
        const int kcur = c * 64;
        const uint32_t base = sb + c * BUFB;
#pragma unroll
        for (int i = 0; i < 4; i++) {
            const int row = lrow + 32 * i;
            const uint32_t d = base + row * ROWB + lg * 16;
            const size_t ea = ((size_t)(m0 + row) * Dd + kcur + lg * 8) * 2;
            cp16(d,             (const char*)g_dhi + ea);
            cp16(d + TILEB,     (const char*)g_dlo + ea);
            const size_t eb = ((size_t)(n0 + row) * Dd + kcur + lg * 8) * 2;
            cp16(d + 2 * TILEB, (const char*)g_w2T_hi + eb);
            cp16(d + 3 * TILEB, (const char*)g_w2T_lo + eb);
        }
        CP_COMMIT();
    }

#pragma unroll
    for (int c = 0; c < 2; c++) {
        if (c < 1) { CP_WAIT(1); } else { CP_WAIT(0); }
        __syncthreads();
        const uint32_t bufA = sb + (c & 1) * BUFB;
#pragma unroll
        for (int k = 0; k < 4; k++) {
            uint32_t ah[2][4], al[2][4];
#pragma unroll
            for (int mf = 0; mf < 2; mf++) {
                const uint32_t ad = bufA + (mbase + mf * 16) * ROWB + k * 32 + aoff;
                ldsm_x4(ah[mf], ad);
                ldsm_x4(al[mf], ad + TILEB);
            }
#pragma unroll
            for (int nl = 0; nl < 4; nl++) {
                const uint32_t bd = bufA + 2 * TILEB
                                  + (nbase + nl * 16) * ROWB + k * 32 + boff;
                uint32_t bh[4], bl[4];
                ldsm_x4(bh, bd);
                ldsm_x4(bl, bd + TILEB);
#pragma unroll
                for (int mf = 0; mf < 2; mf++) {
#pragma unroll
                    for (int h2 = 0; h2 < 2; h2++) {
                        float* a = &accs[(mf * 8 + nl * 2 + h2) * 4];
                        mma_16816(a, ah[mf], &bh[2 * h2]);
                        mma_16816(a, ah[mf], &bl[2 * h2]);
                        mma_16816(a, al[mf], &bh[2 * h2]);
                    }
                }
            }
        }
        __syncthreads();
    }

    // epilogue: logits + bias -> out [B][T][V]
#pragma unroll
    for (int mf = 0; mf < 2; mf++) {
#pragma unroll
        for (int nf = 0; nf < 8; nf++) {
            const float* a = &accs[(mf * 8 + nf) * 4];
            const int col = n0 + nbase + (nf >> 1) * 16 + (nf & 1) * 8 + (lane & 3) * 2;
            if (col >= Vv) continue;
            float2 bv = *(const float2*)(b2 + col);
#pragma unroll
            for (int half = 0; half < 2; half++) {
                const int r = m0 + mbase + mf * 16 + (lane >> 2) + half * 8;
                const int tt = r >> 7, b = r & 127;
                *(float2*)(out + ((size_t)b * Tt + tt) * Vv + col) =
                    make_float2(a[2 * half + 0] + bv.x, a[2 * half + 1] + bv.y);
            }
        }
    }
}

// ---------------------------------------------------------------------------
// Kernel 5: softmax rows of 10000 with logits*50
// ---------------------------------------------------------------------------
__global__ __launch_bounds__(256) void k_softmax(float* __restrict__ out)
{
    float* __restrict__ p = out + (size_t)blockIdx.x * Vv;
    const int tid = threadIdx.x;
    float vals[40];
    float mx = -1e30f;
#pragma unroll
    for (int i = 0; i < 40; i++) {
        int idx = tid + (i << 8);
        if (idx < Vv) {
            float v = p[idx] * 50.0f;
            vals[i] = v;
            mx = fmaxf(mx, v);
        } else {
            vals[i] = -1e30f;
        }
    }
    __shared__ float redm[8];
    __shared__ float reds[8];
#pragma unroll
    for (int o = 16; o; o >>= 1) mx = fmaxf(mx, __shfl_xor_sync(0xffffffffu, mx, o));
    if ((tid & 31) == 0) redm[tid >> 5] = mx;
    __syncthreads();
    mx = redm[0];
#pragma unroll
    for (int w = 1; w < 8; w++) mx = fmaxf(mx, redm[w]);

    float s = 0.f;
#pragma unroll
    for (int i = 0; i < 40; i++) {
        int idx = tid + (i << 8);
        if (idx < Vv) {
            float e = expf(vals[i] - mx);
            vals[i] = e;
            s += e;
        }
    }
#pragma unroll
    for (int o = 16; o; o >>= 1) s += __shfl_xor_sync(0xffffffffu, s, o);
    if ((tid & 31) == 0) reds[tid >> 5] = s;
    __syncthreads();
    float tot = 0.f;
#pragma unroll
    for (int w = 0; w < 8; w++) tot += reds[w];
    float inv = 1.0f / tot;
#pragma unroll
    for (int i = 0; i < 40; i++) {
        int idx = tid + (i << 8);
        if (idx < Vv) p[idx] = vals[i] * inv;
    }
}

// ---------------------------------------------------------------------------
extern "C" void kernel_launch(void* const* d_in, const int* in_sizes, int n_in,
                              void* d_out, int out_size)
{
    const int*   tokens = (const int*)  d_in[0];
    const float* emb    = (const float*)d_in[1];
    const float* gk     = (const float*)d_in[2];
    const float* grk    = (const float*)d_in[3];
    const float* gbi    = (const float*)d_in[4];
    const float* gbr    = (const float*)d_in[5];
    const float* w1     = (const float*)d_in[6];
    const float* b1     = (const float*)d_in[7];
    const float* w2     = (const float*)d_in[8];
    const float* b2     = (const float*)d_in[9];
    float* out = (float*)d_out;

    cudaFuncSetAttribute(k_gru_mma, cudaFuncAttributeMaxDynamicSharedMemorySize, GRU_SMEM);
    cudaFuncSetAttribute(k_w2_mma,  cudaFuncAttributeMaxDynamicSharedMemorySize, GRU_SMEM);

    dim3 blk(256);
    k_reset<<<1, 1>>>();
    k_rk_split<<<dim3(G3 / 32, Hh / 32), blk>>>(grk);
    k_w2split<<<dim3(VvPad / 32, Dd / 32), blk>>>(w2);
    k_embed_gemm<<<dim3(G3 / 64, MROWS / 64), blk>>>(tokens, emb, gk, gbi);
    k_gru_mma<<<GRID_GRU, blk, GRU_SMEM>>>(gbr);
    k_w1relu<<<dim3(Dd / 64, MROWS / 64), blk>>>(w1, b1);
    k_w2_mma<<<dim3(VvPad / 128, MROWS / 128), blk, GRU_SMEM>>>(b2, out);
    k_softmax<<<MROWS, blk>>>(out);
}